// round 2
// baseline (speedup 1.0000x reference)
#include <cuda_runtime.h>
#include <math.h>

#define NB   16
#define SEQ  1024
#define CH   64
#define NC   5
#define MD   96

// ---------------- scratch (device globals; no allocation) ----------------
__device__ float g_w1[NB*SEQ*NC];        // softmax over classes   [b][s][n]
__device__ float g_w2[NB*NC*SEQ];        // softmax over HW        [b][n][s]
__device__ float g_cf[NB*SEQ*CH];        // redistributed features [b][s][c]
__device__ float g_q [NB*4*SEQ*64];      // [b][h][s][d]
__device__ float g_k [NB*4*SEQ*64];
__device__ float g_v [NB*4*SEQ*64];
__device__ float g_o [NB*4*SEQ*64];

// ================= Kernel A: weight = xt@wb_w, both softmaxes =============
__global__ __launch_bounds__(1024) void kA(const float* __restrict__ x,
                                           const float* __restrict__ wbw,
                                           const float* __restrict__ wbb)
{
    const int b = blockIdx.x, s = threadIdx.x;
    __shared__ float ws[CH*NC];
    __shared__ float red[32*NC];
    __shared__ float Mx[NC], Sx[NC];
    if (s < CH*NC) ws[s] = wbw[s];
    __syncthreads();

    const float* xb = x + b*(CH*SEQ) + s;
    float w[NC];
    #pragma unroll
    for (int n=0;n<NC;n++) w[n] = wbb[n];
    #pragma unroll 4
    for (int c=0;c<CH;c++){
        float xv = xb[c<<10];
        #pragma unroll
        for (int n=0;n<NC;n++) w[n] = fmaf(xv, ws[c*NC+n], w[n]);
    }

    // weight1: softmax over n
    {
        float mx = w[0];
        #pragma unroll
        for (int n=1;n<NC;n++) mx = fmaxf(mx, w[n]);
        float e[NC], ssum = 0.f;
        #pragma unroll
        for (int n=0;n<NC;n++){ e[n] = __expf(w[n]-mx); ssum += e[n]; }
        float inv = 1.f/ssum;
        float* w1p = g_w1 + b*(SEQ*NC) + s*NC;
        #pragma unroll
        for (int n=0;n<NC;n++) w1p[n] = e[n]*inv;
    }

    // weight2: softmax over s (block reductions per class)
    const int lane = s & 31, wid = s >> 5;
    float r5[NC];
    #pragma unroll
    for (int n=0;n<NC;n++) r5[n] = w[n];
    #pragma unroll
    for (int off=16; off; off>>=1)
        #pragma unroll
        for (int n=0;n<NC;n++) r5[n] = fmaxf(r5[n], __shfl_xor_sync(0xffffffffu, r5[n], off));
    if (lane==0){
        #pragma unroll
        for (int n=0;n<NC;n++) red[wid*NC+n] = r5[n];
    }
    __syncthreads();
    if (wid==0){
        #pragma unroll
        for (int n=0;n<NC;n++) r5[n] = red[lane*NC+n];
        #pragma unroll
        for (int off=16; off; off>>=1)
            #pragma unroll
            for (int n=0;n<NC;n++) r5[n] = fmaxf(r5[n], __shfl_xor_sync(0xffffffffu, r5[n], off));
        if (lane==0){
            #pragma unroll
            for (int n=0;n<NC;n++) Mx[n] = r5[n];
        }
    }
    __syncthreads();
    float e2[NC];
    #pragma unroll
    for (int n=0;n<NC;n++){ e2[n] = __expf(w[n]-Mx[n]); r5[n] = e2[n]; }
    #pragma unroll
    for (int off=16; off; off>>=1)
        #pragma unroll
        for (int n=0;n<NC;n++) r5[n] += __shfl_xor_sync(0xffffffffu, r5[n], off);
    if (lane==0){
        #pragma unroll
        for (int n=0;n<NC;n++) red[wid*NC+n] = r5[n];
    }
    __syncthreads();
    if (wid==0){
        #pragma unroll
        for (int n=0;n<NC;n++) r5[n] = red[lane*NC+n];
        #pragma unroll
        for (int off=16; off; off>>=1)
            #pragma unroll
            for (int n=0;n<NC;n++) r5[n] += __shfl_xor_sync(0xffffffffu, r5[n], off);
        if (lane==0){
            #pragma unroll
            for (int n=0;n<NC;n++) Sx[n] = r5[n];
        }
    }
    __syncthreads();
    float* w2p = g_w2 + b*(NC*SEQ) + s;
    #pragma unroll
    for (int n=0;n<NC;n++) w2p[n<<10] = e2[n] / Sx[n];
}

// ====== Kernel B: class pooling, MHA1 (5 tokens vs memory), redistribute ===
__global__ __launch_bounds__(512) void kB(const float* __restrict__ x,
    const float* __restrict__ memory,
    const float* __restrict__ wq, const float* __restrict__ bq,
    const float* __restrict__ wk, const float* __restrict__ bk,
    const float* __restrict__ wv, const float* __restrict__ bv,
    const float* __restrict__ fc, const float* __restrict__ fcb,
    const float* __restrict__ lng, const float* __restrict__ lnb)
{
    const int b = blockIdx.x, tid = threadIdx.x;
    __shared__ float xs[64*65];
    __shared__ float w2s[NC*64];
    __shared__ float cf1s[NC*64];
    __shared__ float mems[NC*MD];
    __shared__ float qh[NC*MD], kh[NC*MD], vh[NC*64];
    __shared__ float Ssm[NC*NC];
    __shared__ float osm[NC*64];
    __shared__ float projs[NC*64];

    // class_feat1 = weight2 @ xt  (tile over s)
    float acc = 0.f;
    for (int st=0; st<16; st++){
        __syncthreads();
        const int s0 = st*64;
        #pragma unroll
        for (int i=0;i<8;i++){
            int idx = i*512 + tid;
            int c = idx>>6, sl = idx&63;
            xs[c*65+sl] = x[b*65536 + (c<<10) + s0 + sl];
        }
        if (tid < 320)
            w2s[tid] = g_w2[b*5120 + ((tid>>6)<<10) + s0 + (tid&63)];
        __syncthreads();
        if (tid < 320){
            const int n = tid>>6, c = tid&63;
            float a = 0.f;
            #pragma unroll 8
            for (int sl=0; sl<64; sl++) a = fmaf(w2s[n*64+sl], xs[c*65+sl], a);
            acc += a;
        }
    }
    if (tid < 320) cf1s[tid] = acc;
    if (tid < NC*MD) mems[tid] = memory[tid];
    __syncthreads();

    // qh (scaled by 1/sqrt(96)), kh, vh
    if (tid < 480){
        const int n = tid/96, j = tid - n*96;
        float q = bq[j];
        #pragma unroll
        for (int d=0; d<64; d++) q = fmaf(cf1s[n*64+d], wq[d*96+j], q);
        qh[tid] = q * 0.102062072615966f;
        float kk = bk[j];
        #pragma unroll
        for (int d=0; d<96; d++) kk = fmaf(mems[n*96+d], wk[d*96+j], kk);
        kh[tid] = kk;
    }
    if (tid < 320){
        const int n = tid>>6, c = tid&63;
        float vv = bv[c];
        #pragma unroll
        for (int d=0; d<96; d++) vv = fmaf(mems[n*96+d], wv[d*64+c], vv);
        vh[tid] = vv;
    }
    __syncthreads();

    if (tid < 25){
        const int i = tid/5, j = tid - (tid/5)*5;
        float sv = 0.f;
        #pragma unroll
        for (int d=0; d<96; d++) sv = fmaf(qh[i*96+d], kh[j*96+d], sv);
        Ssm[tid] = sv;
    }
    __syncthreads();
    if (tid < 5){
        float m = Ssm[tid*5];
        #pragma unroll
        for (int j=1;j<5;j++) m = fmaxf(m, Ssm[tid*5+j]);
        float p[5], sum = 0.f;
        #pragma unroll
        for (int j=0;j<5;j++){ p[j] = __expf(Ssm[tid*5+j]-m); sum += p[j]; }
        float inv = 1.f/sum;
        #pragma unroll
        for (int j=0;j<5;j++) Ssm[tid*5+j] = p[j]*inv;
    }
    __syncthreads();
    if (tid < 320){
        const int n = tid>>6, c = tid&63;
        float o = 0.f;
        #pragma unroll
        for (int j=0;j<5;j++) o = fmaf(Ssm[n*5+j], vh[j*64+c], o);
        osm[tid] = o;
    }
    __syncthreads();
    if (tid < 320){
        const int n = tid>>6, c = tid&63;
        float p = fcb[c] + cf1s[tid];
        #pragma unroll
        for (int k=0;k<64;k++) p = fmaf(osm[n*64+k], fc[k*64+c], p);
        projs[tid] = p;
    }
    __syncthreads();
    // post-LN (5 rows of 64): warp n handles row n
    if (tid < 160){
        const int n = tid>>5, lane = tid&31;
        float v0 = projs[n*64+lane], v1 = projs[n*64+lane+32];
        float sm = v0+v1, sq = v0*v0 + v1*v1;
        #pragma unroll
        for (int off=16; off; off>>=1){
            sm += __shfl_xor_sync(0xffffffffu, sm, off);
            sq += __shfl_xor_sync(0xffffffffu, sq, off);
        }
        float mu = sm*(1.f/64.f);
        float var = sq*(1.f/64.f) - mu*mu;
        float rs = rsqrtf(var + 1e-6f);
        cf1s[n*64+lane]    = (v0-mu)*rs*lng[lane]    + lnb[lane];
        cf1s[n*64+lane+32] = (v1-mu)*rs*lng[lane+32] + lnb[lane+32];
    }
    __syncthreads();
    // redistribute: cf = weight1 @ cf1
    for (int it=0; it<128; it++){
        int idx = it*512 + tid;
        int s = idx>>6, c = idx&63;
        const float* w1p = g_w1 + b*5120 + s*5;
        float a = 0.f;
        #pragma unroll
        for (int n=0;n<5;n++) a = fmaf(w1p[n], cf1s[n*64+c], a);
        g_cf[b*65536 + idx] = a;
    }
}

// ============ Kernel C: QKV projection GEMM [16384,64]@[64,256] ============
__global__ __launch_bounds__(256) void kC(const float* __restrict__ w,
                                          const float* __restrict__ bias,
                                          float* __restrict__ outp)
{
    __shared__ float As[64*64];
    __shared__ float Bs[64*65];
    const int mt = blockIdx.x, h = blockIdx.y, tid = threadIdx.x;
    const int tx = tid&15, ty = tid>>4;
    const int m0 = mt*64;
    #pragma unroll
    for (int i=0;i<16;i++){
        int idx = i*256 + tid;
        As[idx] = g_cf[m0*64 + idx];
        int k = idx>>6, n = idx&63;
        Bs[k*65+n] = w[k*256 + h*64 + n];
    }
    __syncthreads();
    float accm[4][4] = {};
    #pragma unroll 8
    for (int k=0;k<64;k++){
        float a[4], bb[4];
        #pragma unroll
        for (int i=0;i<4;i++) a[i] = As[(4*ty+i)*64 + k];
        #pragma unroll
        for (int j=0;j<4;j++) bb[j] = Bs[k*65 + 4*tx + j];
        #pragma unroll
        for (int i=0;i<4;i++)
            #pragma unroll
            for (int j=0;j<4;j++) accm[i][j] = fmaf(a[i], bb[j], accm[i][j]);
    }
    const int bb_ = m0 >> 10;
    const int s0  = m0 & 1023;
    float* op = outp + ((bb_*4 + h) << 16);
    #pragma unroll
    for (int i=0;i<4;i++){
        int r = 4*ty + i;
        #pragma unroll
        for (int j=0;j<4;j++){
            int d = 4*tx + j;
            op[(s0+r)*64 + d] = accm[i][j] + bias[h*64 + d];
        }
    }
}

// ========== Kernel D: flash attention per (q-tile, head, batch) ============
__global__ __launch_bounds__(256) void kD()
{
    extern __shared__ float dyn[];
    float* Qs = dyn;                  // 64x64
    float* Ks = dyn + 4096;           // 64x65 (P tile aliases this)
    float* Vs = dyn + 4096 + 4160;    // 64x64
    const int qt = blockIdx.x, h = blockIdx.y, b = blockIdx.z;
    const int tid = threadIdx.x, tx = tid&15, ty = tid>>4;
    const int base = ((b*4 + h) << 16);

    const float* Qp = g_q + base + qt*4096;
    #pragma unroll
    for (int i=0;i<16;i++){ int idx=i*256+tid; Qs[idx] = Qp[idx]*0.125f; }

    float O[4][4] = {};
    float m[4], l[4];
    #pragma unroll
    for (int i=0;i<4;i++){ m[i] = -1e30f; l[i] = 0.f; }

    for (int kt=0; kt<16; kt++){
        __syncthreads();                       // prev O-phase done with Ks/Vs
        const float* Kp = g_k + base + kt*4096;
        const float* Vp = g_v + base + kt*4096;
        #pragma unroll
        for (int i=0;i<16;i++){
            int idx = i*256 + tid;
            int c = idx>>6, d = idx&63;
            Ks[c*65+d] = Kp[idx];
            Vs[idx]    = Vp[idx];
        }
        __syncthreads();

        float S4[4][4] = {};
        #pragma unroll 8
        for (int d=0; d<64; d++){
            float a[4], kv[4];
            #pragma unroll
            for (int i=0;i<4;i++) a[i]  = Qs[(4*ty+i)*64 + d];
            #pragma unroll
            for (int j=0;j<4;j++) kv[j] = Ks[(4*tx+j)*65 + d];
            #pragma unroll
            for (int i=0;i<4;i++)
                #pragma unroll
                for (int j=0;j<4;j++) S4[i][j] = fmaf(a[i], kv[j], S4[i][j]);
        }

        // online softmax (row groups of 16 lanes share rows)
        #pragma unroll
        for (int i=0;i<4;i++){
            float mr = S4[i][0];
            #pragma unroll
            for (int j=1;j<4;j++) mr = fmaxf(mr, S4[i][j]);
            #pragma unroll
            for (int off=8; off; off>>=1) mr = fmaxf(mr, __shfl_xor_sync(0xffffffffu, mr, off));
            float mn = fmaxf(m[i], mr);
            float alpha = __expf(m[i]-mn);
            float rs = 0.f;
            #pragma unroll
            for (int j=0;j<4;j++){ S4[i][j] = __expf(S4[i][j]-mn); rs += S4[i][j]; }
            #pragma unroll
            for (int off=8; off; off>>=1) rs += __shfl_xor_sync(0xffffffffu, rs, off);
            l[i] = l[i]*alpha + rs;
            m[i] = mn;
            #pragma unroll
            for (int j=0;j<4;j++) O[i][j] *= alpha;
        }

        __syncthreads();                       // all lanes done reading Ks
        #pragma unroll
        for (int i=0;i<4;i++)
            #pragma unroll
            for (int j=0;j<4;j++)
                Ks[(4*ty+i)*65 + 4*tx+j] = S4[i][j];   // P tile
        __syncthreads();

        #pragma unroll 8
        for (int jj=0; jj<64; jj++){
            float p[4], vv[4];
            #pragma unroll
            for (int i=0;i<4;i++) p[i]  = Ks[(4*ty+i)*65 + jj];
            #pragma unroll
            for (int j=0;j<4;j++) vv[j] = Vs[jj*64 + 4*tx+j];
            #pragma unroll
            for (int i=0;i<4;i++)
                #pragma unroll
                for (int j=0;j<4;j++) O[i][j] = fmaf(p[i], vv[j], O[i][j]);
        }
    }

    float* Op = g_o + base + qt*4096;
    #pragma unroll
    for (int i=0;i<4;i++){
        float invl = 1.f / l[i];
        #pragma unroll
        for (int j=0;j<4;j++)
            Op[(4*ty+i)*64 + 4*tx+j] = O[i][j]*invl;
    }
}

// ==== Kernel E: out-proj GEMM [*,256]@[256,64] + residual + LN + transpose =
__global__ __launch_bounds__(256) void kE(const float* __restrict__ fc,
                                          const float* __restrict__ fcb,
                                          const float* __restrict__ lng,
                                          const float* __restrict__ lnb,
                                          float* __restrict__ out)
{
    __shared__ float As[64*64];
    __shared__ float Bs[64*65];
    float* Cs = Bs;                    // alias: Bs dead after last GEMM chunk
    const int stile = blockIdx.x, b = blockIdx.y, tid = threadIdx.x;
    const int tx = tid&15, ty = tid>>4;
    const int s0 = stile*64;

    float accv[4][4] = {};
    for (int h=0; h<4; h++){
        __syncthreads();
        const float* Ap = g_o + ((b*4+h)<<16) + s0*64;
        #pragma unroll
        for (int i=0;i<16;i++){
            int idx = i*256 + tid;
            As[idx] = Ap[idx];
            int k = idx>>6, c = idx&63;
            Bs[k*65+c] = fc[(h*64+k)*64 + c];
        }
        __syncthreads();
        #pragma unroll 8
        for (int k=0;k<64;k++){
            float a[4], bb[4];
            #pragma unroll
            for (int i=0;i<4;i++) a[i] = As[(4*ty+i)*64 + k];
            #pragma unroll
            for (int j=0;j<4;j++) bb[j] = Bs[k*65 + 4*tx + j];
            #pragma unroll
            for (int i=0;i<4;i++)
                #pragma unroll
                for (int j=0;j<4;j++) accv[i][j] = fmaf(a[i], bb[j], accv[i][j]);
        }
    }
    __syncthreads();
    #pragma unroll
    for (int i=0;i<4;i++){
        int r = 4*ty + i;
        #pragma unroll
        for (int j=0;j<4;j++){
            int c = 4*tx + j;
            Cs[r*65+c] = accv[i][j] + fcb[c] + g_cf[b*65536 + (s0+r)*64 + c];
        }
    }
    __syncthreads();
    {   // LN per row: 8 warps x 8 rows
        const int wid = tid>>5, lane = tid&31;
        for (int rr=0; rr<8; rr++){
            int r = wid*8 + rr;
            float v0 = Cs[r*65+lane], v1 = Cs[r*65+lane+32];
            float sm = v0+v1, sq = v0*v0 + v1*v1;
            #pragma unroll
            for (int off=16; off; off>>=1){
                sm += __shfl_xor_sync(0xffffffffu, sm, off);
                sq += __shfl_xor_sync(0xffffffffu, sq, off);
            }
            float mu = sm*(1.f/64.f);
            float var = sq*(1.f/64.f) - mu*mu;
            float rstd = rsqrtf(var + 1e-6f);
            Cs[r*65+lane]    = (v0-mu)*rstd*lng[lane]    + lnb[lane];
            Cs[r*65+lane+32] = (v1-mu)*rstd*lng[lane+32] + lnb[lane+32];
        }
    }
    __syncthreads();
    #pragma unroll
    for (int i=0;i<16;i++){
        int idx = i*256 + tid;
        int c = idx>>6, sl = idx&63;
        out[(((b<<6)+c)<<10) + s0 + sl] = Cs[sl*65+c];
    }
}

// ============================== launcher ===================================
extern "C" void kernel_launch(void* const* d_in, const int* in_sizes, int n_in,
                              void* d_out, int out_size)
{
    const float* x      = (const float*)d_in[0];
    const float* memory = (const float*)d_in[1];
    const float* wb_w   = (const float*)d_in[2];
    const float* wb_b   = (const float*)d_in[3];
    const float* a1_wq  = (const float*)d_in[4];
    const float* a1_bq  = (const float*)d_in[5];
    const float* a1_wk  = (const float*)d_in[6];
    const float* a1_bk  = (const float*)d_in[7];
    const float* a1_wv  = (const float*)d_in[8];
    const float* a1_bv  = (const float*)d_in[9];
    const float* a1_fc  = (const float*)d_in[10];
    const float* a1_fcb = (const float*)d_in[11];
    const float* a1_lng = (const float*)d_in[12];
    const float* a1_lnb = (const float*)d_in[13];
    const float* a2_wq  = (const float*)d_in[14];
    const float* a2_bq  = (const float*)d_in[15];
    const float* a2_wk  = (const float*)d_in[16];
    const float* a2_bk  = (const float*)d_in[17];
    const float* a2_wv  = (const float*)d_in[18];
    const float* a2_bv  = (const float*)d_in[19];
    const float* a2_fc  = (const float*)d_in[20];
    const float* a2_fcb = (const float*)d_in[21];
    const float* a2_lng = (const float*)d_in[22];
    const float* a2_lnb = (const float*)d_in[23];
    float* out = (float*)d_out;

    float *pq=0, *pk=0, *pv=0;
    cudaGetSymbolAddress((void**)&pq, g_q);
    cudaGetSymbolAddress((void**)&pk, g_k);
    cudaGetSymbolAddress((void**)&pv, g_v);

    const int kd_smem = (4096 + 4160 + 4096) * 4;   // 49408 B
    cudaFuncSetAttribute(kD, cudaFuncAttributeMaxDynamicSharedMemorySize, kd_smem);

    kA<<<NB, 1024>>>(x, wb_w, wb_b);
    kB<<<NB, 512>>>(x, memory, a1_wq, a1_bq, a1_wk, a1_bk, a1_wv, a1_bv,
                    a1_fc, a1_fcb, a1_lng, a1_lnb);
    dim3 gC(256, 4);
    kC<<<gC, 256>>>(a2_wq, a2_bq, pq);
    kC<<<gC, 256>>>(a2_wk, a2_bk, pk);
    kC<<<gC, 256>>>(a2_wv, a2_bv, pv);
    dim3 gD(16, 4, NB);
    kD<<<gD, 256, kd_smem>>>();
    dim3 gE(16, NB);
    kE<<<gE, 256>>>(a2_fc, a2_fcb, a2_lng, a2_lnb, out);
}

// round 3
// speedup vs baseline: 4.1275x; 4.1275x over previous
#include <cuda_runtime.h>
#include <math.h>

#define NB   16
#define SEQ  1024
#define CH   64
#define NC   5
#define MD   96

// ---------------- scratch (device globals; no allocation) ----------------
__device__ float g_w1[NB*SEQ*NC];
__device__ float g_w2[NB*NC*SEQ];
__device__ float g_cf[NB*SEQ*CH];
__device__ float g_q [NB*4*SEQ*64];
__device__ float g_k [NB*4*SEQ*64];
__device__ float g_v [NB*4*SEQ*64];
__device__ float g_o [NB*4*SEQ*64];

// ---------------- helpers ----------------
__device__ __forceinline__ float tf32r(float x){
    unsigned u; asm("cvt.rna.tf32.f32 %0, %1;" : "=r"(u) : "f"(x));
    return __uint_as_float(u);
}
__device__ __forceinline__ unsigned tf32u(float x){
    unsigned u; asm("cvt.rna.tf32.f32 %0, %1;" : "=r"(u) : "f"(x));
    return u;
}
__device__ __forceinline__ void cp16(void* dst, const void* src){
    unsigned d = (unsigned)__cvta_generic_to_shared(dst);
    asm volatile("cp.async.cg.shared.global [%0], [%1], 16;" :: "r"(d), "l"(src));
}
#define CP_COMMIT asm volatile("cp.async.commit_group;")
#define CP_WAIT0  asm volatile("cp.async.wait_group 0;")

#define MMA_TF32(c0,c1,c2,c3,a0,a1,a2,a3,b0,b1)                               \
  asm volatile("mma.sync.aligned.m16n8k8.row.col.f32.tf32.tf32.f32 "          \
    "{%0,%1,%2,%3}, {%4,%5,%6,%7}, {%8,%9}, {%0,%1,%2,%3};"                   \
    : "+f"(c0),"+f"(c1),"+f"(c2),"+f"(c3)                                     \
    : "r"(a0),"r"(a1),"r"(a2),"r"(a3),"r"(b0),"r"(b1))

// ================= Kernel A: weight = xt@wb_w, both softmaxes =============
__global__ __launch_bounds__(1024) void kA(const float* __restrict__ x,
                                           const float* __restrict__ wbw,
                                           const float* __restrict__ wbb)
{
    const int b = blockIdx.x, s = threadIdx.x;
    __shared__ float ws[CH*NC];
    __shared__ float red[32*NC];
    __shared__ float Mx[NC], Sx[NC];
    if (s < CH*NC) ws[s] = wbw[s];
    __syncthreads();

    const float* xb = x + b*(CH*SEQ) + s;
    float w[NC];
    #pragma unroll
    for (int n=0;n<NC;n++) w[n] = wbb[n];
    #pragma unroll 8
    for (int c=0;c<CH;c++){
        float xv = xb[c<<10];
        #pragma unroll
        for (int n=0;n<NC;n++) w[n] = fmaf(xv, ws[c*NC+n], w[n]);
    }

    {
        float mx = w[0];
        #pragma unroll
        for (int n=1;n<NC;n++) mx = fmaxf(mx, w[n]);
        float e[NC], ssum = 0.f;
        #pragma unroll
        for (int n=0;n<NC;n++){ e[n] = __expf(w[n]-mx); ssum += e[n]; }
        float inv = 1.f/ssum;
        float* w1p = g_w1 + b*(SEQ*NC) + s*NC;
        #pragma unroll
        for (int n=0;n<NC;n++) w1p[n] = e[n]*inv;
    }

    const int lane = s & 31, wid = s >> 5;
    float r5[NC];
    #pragma unroll
    for (int n=0;n<NC;n++) r5[n] = w[n];
    #pragma unroll
    for (int off=16; off; off>>=1)
        #pragma unroll
        for (int n=0;n<NC;n++) r5[n] = fmaxf(r5[n], __shfl_xor_sync(0xffffffffu, r5[n], off));
    if (lane==0){
        #pragma unroll
        for (int n=0;n<NC;n++) red[wid*NC+n] = r5[n];
    }
    __syncthreads();
    if (wid==0){
        #pragma unroll
        for (int n=0;n<NC;n++) r5[n] = red[lane*NC+n];
        #pragma unroll
        for (int off=16; off; off>>=1)
            #pragma unroll
            for (int n=0;n<NC;n++) r5[n] = fmaxf(r5[n], __shfl_xor_sync(0xffffffffu, r5[n], off));
        if (lane==0){
            #pragma unroll
            for (int n=0;n<NC;n++) Mx[n] = r5[n];
        }
    }
    __syncthreads();
    float e2[NC];
    #pragma unroll
    for (int n=0;n<NC;n++){ e2[n] = __expf(w[n]-Mx[n]); r5[n] = e2[n]; }
    #pragma unroll
    for (int off=16; off; off>>=1)
        #pragma unroll
        for (int n=0;n<NC;n++) r5[n] += __shfl_xor_sync(0xffffffffu, r5[n], off);
    if (lane==0){
        #pragma unroll
        for (int n=0;n<NC;n++) red[wid*NC+n] = r5[n];
    }
    __syncthreads();
    if (wid==0){
        #pragma unroll
        for (int n=0;n<NC;n++) r5[n] = red[lane*NC+n];
        #pragma unroll
        for (int off=16; off; off>>=1)
            #pragma unroll
            for (int n=0;n<NC;n++) r5[n] += __shfl_xor_sync(0xffffffffu, r5[n], off);
        if (lane==0){
            #pragma unroll
            for (int n=0;n<NC;n++) Sx[n] = r5[n];
        }
    }
    __syncthreads();
    float* w2p = g_w2 + b*(NC*SEQ) + s;
    #pragma unroll
    for (int n=0;n<NC;n++) w2p[n<<10] = e2[n] / Sx[n];
}

// ====== Kernel B: class pooling, MHA1 (5 tokens vs memory), redistribute ===
__global__ __launch_bounds__(512) void kB(const float* __restrict__ x,
    const float* __restrict__ memory,
    const float* __restrict__ wq, const float* __restrict__ bq,
    const float* __restrict__ wk, const float* __restrict__ bk,
    const float* __restrict__ wv, const float* __restrict__ bv,
    const float* __restrict__ fc, const float* __restrict__ fcb,
    const float* __restrict__ lng, const float* __restrict__ lnb)
{
    const int b = blockIdx.x, tid = threadIdx.x;
    __shared__ float xs[64*65];
    __shared__ float w2s[NC*64];
    __shared__ float cf1s[NC*64];
    __shared__ float mems[NC*MD];
    __shared__ float qh[NC*MD], kh[NC*MD], vh[NC*64];
    __shared__ float Ssm[NC*NC];
    __shared__ float osm[NC*64];
    __shared__ float projs[NC*64];

    float acc = 0.f;
    for (int st=0; st<16; st++){
        __syncthreads();
        const int s0 = st*64;
        #pragma unroll
        for (int i=0;i<8;i++){
            int idx = i*512 + tid;
            int c = idx>>6, sl = idx&63;
            xs[c*65+sl] = x[b*65536 + (c<<10) + s0 + sl];
        }
        if (tid < 320)
            w2s[tid] = g_w2[b*5120 + ((tid>>6)<<10) + s0 + (tid&63)];
        __syncthreads();
        if (tid < 320){
            const int n = tid>>6, c = tid&63;
            float a = 0.f;
            #pragma unroll 8
            for (int sl=0; sl<64; sl++) a = fmaf(w2s[n*64+sl], xs[c*65+sl], a);
            acc += a;
        }
    }
    if (tid < 320) cf1s[tid] = acc;
    if (tid < NC*MD) mems[tid] = memory[tid];
    __syncthreads();

    if (tid < 480){
        const int n = tid/96, j = tid - n*96;
        float q = bq[j];
        #pragma unroll
        for (int d=0; d<64; d++) q = fmaf(cf1s[n*64+d], wq[d*96+j], q);
        qh[tid] = q * 0.102062072615966f;
        float kk = bk[j];
        #pragma unroll
        for (int d=0; d<96; d++) kk = fmaf(mems[n*96+d], wk[d*96+j], kk);
        kh[tid] = kk;
    }
    if (tid < 320){
        const int n = tid>>6, c = tid&63;
        float vv = bv[c];
        #pragma unroll
        for (int d=0; d<96; d++) vv = fmaf(mems[n*96+d], wv[d*64+c], vv);
        vh[tid] = vv;
    }
    __syncthreads();

    if (tid < 25){
        const int i = tid/5, j = tid - (tid/5)*5;
        float sv = 0.f;
        #pragma unroll
        for (int d=0; d<96; d++) sv = fmaf(qh[i*96+d], kh[j*96+d], sv);
        Ssm[tid] = sv;
    }
    __syncthreads();
    if (tid < 5){
        float m = Ssm[tid*5];
        #pragma unroll
        for (int j=1;j<5;j++) m = fmaxf(m, Ssm[tid*5+j]);
        float p[5], sum = 0.f;
        #pragma unroll
        for (int j=0;j<5;j++){ p[j] = __expf(Ssm[tid*5+j]-m); sum += p[j]; }
        float inv = 1.f/sum;
        #pragma unroll
        for (int j=0;j<5;j++) Ssm[tid*5+j] = p[j]*inv;
    }
    __syncthreads();
    if (tid < 320){
        const int n = tid>>6, c = tid&63;
        float o = 0.f;
        #pragma unroll
        for (int j=0;j<5;j++) o = fmaf(Ssm[n*5+j], vh[j*64+c], o);
        osm[tid] = o;
    }
    __syncthreads();
    if (tid < 320){
        const int n = tid>>6, c = tid&63;
        float p = fcb[c] + cf1s[tid];
        #pragma unroll
        for (int k=0;k<64;k++) p = fmaf(osm[n*64+k], fc[k*64+c], p);
        projs[tid] = p;
    }
    __syncthreads();
    if (tid < 160){
        const int n = tid>>5, lane = tid&31;
        float v0 = projs[n*64+lane], v1 = projs[n*64+lane+32];
        float sm = v0+v1, sq = v0*v0 + v1*v1;
        #pragma unroll
        for (int off=16; off; off>>=1){
            sm += __shfl_xor_sync(0xffffffffu, sm, off);
            sq += __shfl_xor_sync(0xffffffffu, sq, off);
        }
        float mu = sm*(1.f/64.f);
        float var = sq*(1.f/64.f) - mu*mu;
        float rs = rsqrtf(var + 1e-6f);
        cf1s[n*64+lane]    = (v0-mu)*rs*lng[lane]    + lnb[lane];
        cf1s[n*64+lane+32] = (v1-mu)*rs*lng[lane+32] + lnb[lane+32];
    }
    __syncthreads();
    for (int it=0; it<128; it++){
        int idx = it*512 + tid;
        int s = idx>>6, c = idx&63;
        const float* w1p = g_w1 + b*5120 + s*5;
        float a = 0.f;
        #pragma unroll
        for (int n=0;n<5;n++) a = fmaf(w1p[n], cf1s[n*64+c], a);
        g_cf[b*65536 + idx] = a;
    }
}

// ====== Kernel Cm: fused QKV projection via tf32 mma ======================
// C[16384,256] = cf[16384,64] @ W[64,256] + bias, z selects Q/K/V.
// Output rounded to tf32 (rna) so kD can feed raw bits into HMMA.
__global__ __launch_bounds__(256) void kCm(
    const float* __restrict__ wq, const float* __restrict__ wk, const float* __restrict__ wv,
    const float* __restrict__ bq, const float* __restrict__ bk, const float* __restrict__ bv,
    float* __restrict__ pq, float* __restrict__ pk, float* __restrict__ pv)
{
    extern __shared__ float smc[];
    float* Ast = smc;          // [128][68]
    float* Ws  = smc + 8704;   // [64][136]
    float* bs  = smc + 17408;  // [128]
    const int mt=blockIdx.x, nt=blockIdx.y, z=blockIdx.z;
    const int tid=threadIdx.x, w=tid>>5, lane=tid&31, gid=lane>>2, l4=lane&3;
    const float* W  = (z==0)?wq:((z==1)?wk:wv);
    const float* Bp = (z==0)?bq:((z==1)?bk:bv);
    float*       O  = (z==0)?pq:((z==1)?pk:pv);

    const float* Ap = g_cf + mt*128*64;
    #pragma unroll
    for (int i=0;i<8;i++){
        int idx=i*256+tid, row=idx>>4, c4=(idx&15)*4;
        *(float4*)(Ast + row*68 + c4) = *(const float4*)(Ap + row*64 + c4);
    }
    #pragma unroll
    for (int i=0;i<8;i++){
        int idx=i*256+tid, row=idx>>5, c4=(idx&31)*4;
        *(float4*)(Ws + row*136 + c4) = *(const float4*)(W + row*256 + nt*128 + c4);
    }
    if (tid<128) bs[tid] = Bp[nt*128+tid];
    __syncthreads();

    unsigned af[8][4];
    const int r0 = w*16;
    #pragma unroll
    for (int kk=0;kk<8;kk++){
        af[kk][0]=__float_as_uint(Ast[(r0+gid  )*68 + kk*8   + l4]);
        af[kk][1]=__float_as_uint(Ast[(r0+gid+8)*68 + kk*8   + l4]);
        af[kk][2]=__float_as_uint(Ast[(r0+gid  )*68 + kk*8+4 + l4]);
        af[kk][3]=__float_as_uint(Ast[(r0+gid+8)*68 + kk*8+4 + l4]);
    }
    float c[16][4];
    #pragma unroll
    for (int j=0;j<16;j++){ c[j][0]=c[j][1]=c[j][2]=c[j][3]=0.f; }
    #pragma unroll
    for (int j=0;j<16;j++){
        #pragma unroll
        for (int kk=0;kk<8;kk++){
            unsigned b0=__float_as_uint(Ws[(kk*8+l4  )*136 + j*8+gid]);
            unsigned b1=__float_as_uint(Ws[(kk*8+l4+4)*136 + j*8+gid]);
            MMA_TF32(c[j][0],c[j][1],c[j][2],c[j][3],
                     af[kk][0],af[kk][1],af[kk][2],af[kk][3],b0,b1);
        }
    }
    const int row_lo = mt*128 + r0 + gid;
    const int bidx = row_lo>>10, s_lo = row_lo&1023;
    #pragma unroll
    for (int j=0;j<16;j++){
        int cl = j*8 + 2*l4;
        int col = nt*128 + cl;
        int h = col>>6, d = col&63;
        float* op = O + (((bidx<<2)+h)<<16);
        float2 vlo = make_float2(tf32r(c[j][0]+bs[cl]), tf32r(c[j][1]+bs[cl+1]));
        float2 vhi = make_float2(tf32r(c[j][2]+bs[cl]), tf32r(c[j][3]+bs[cl+1]));
        *(float2*)(op + s_lo*64 + d)     = vlo;
        *(float2*)(op + (s_lo+8)*64 + d) = vhi;
    }
}

// ========== Kernel D: tf32 mma flash attention ============================
// CTA: 256 thr / 8 warps, 128 q-rows; K/V tiles of 128 rows, double-buffered
// via cp.async. Per-warp: S[16x128] accum, O[16x64] accum, Q frags in regs.
__global__ __launch_bounds__(256) void kD()
{
    extern __shared__ float sm[];
    float* KS0 = sm;             // [128][68]
    float* VS0 = sm + 8704;      // [128][72]
    float* KS1 = sm + 17920;     // [128][68]
    float* VS1 = sm + 26624;     // [128][72]
    float* Qst = KS1;            // alias (used before loop only)

    const int qt=blockIdx.x, h=blockIdx.y, b=blockIdx.z;
    const int tid=threadIdx.x, w=tid>>5, lane=tid&31;
    const int gid=lane>>2, l4=lane&3;
    const int base=((b*4+h)<<16);

    const float* Kg = g_k + base;
    const float* Vg = g_v + base;
    const float* Qg = g_q + base + qt*8192;

    // prefetch tile 0 into buf0
    #pragma unroll
    for (int i=0;i<8;i++){
        int idx=i*256+tid, row=idx>>4, c4=(idx&15)*4;
        cp16(KS0 + row*68 + c4, Kg + row*64 + c4);
        cp16(VS0 + row*72 + c4, Vg + row*64 + c4);
    }
    CP_COMMIT;

    // stage Q (scaled by 1/sqrt(64)); g_q already tf32-rounded
    #pragma unroll
    for (int i=0;i<8;i++){
        int idx=i*256+tid, row=idx>>4, c4=(idx&15)*4;
        float4 v = *(const float4*)(Qg + row*64 + c4);
        Qst[row*68+c4+0]=v.x*0.125f; Qst[row*68+c4+1]=v.y*0.125f;
        Qst[row*68+c4+2]=v.z*0.125f; Qst[row*68+c4+3]=v.w*0.125f;
    }
    __syncthreads();
    unsigned qf[8][4];
    const int r0 = w*16;
    #pragma unroll
    for (int kk=0;kk<8;kk++){
        qf[kk][0]=__float_as_uint(Qst[(r0+gid  )*68 + kk*8   + l4]);
        qf[kk][1]=__float_as_uint(Qst[(r0+gid+8)*68 + kk*8   + l4]);
        qf[kk][2]=__float_as_uint(Qst[(r0+gid  )*68 + kk*8+4 + l4]);
        qf[kk][3]=__float_as_uint(Qst[(r0+gid+8)*68 + kk*8+4 + l4]);
    }
    __syncthreads();   // done with Qst before buf1 gets K/V

    float o[8][4];
    #pragma unroll
    for (int n=0;n<8;n++){ o[n][0]=o[n][1]=o[n][2]=o[n][3]=0.f; }
    float m_lo=-1e30f, m_hi=-1e30f, l_lo=0.f, l_hi=0.f;

    const int src0 = (lane & ~3) | (l4>>1);
    const int src1 = src0 | 2;
    const bool odd = (l4&1);

    for (int kt=0; kt<8; kt++){
        CP_WAIT0;
        __syncthreads();   // tile kt ready; all warps done with other buffer
        if (kt<7){
            const float* Kp = Kg + (kt+1)*8192;
            const float* Vp = Vg + (kt+1)*8192;
            float* kd = ((kt+1)&1) ? KS1 : KS0;
            float* vd = ((kt+1)&1) ? VS1 : VS0;
            #pragma unroll
            for (int i=0;i<8;i++){
                int idx=i*256+tid, row=idx>>4, c4=(idx&15)*4;
                cp16(kd + row*68 + c4, Kp + row*64 + c4);
                cp16(vd + row*72 + c4, Vp + row*64 + c4);
            }
            CP_COMMIT;
        }
        const float* Ks_ = (kt&1) ? KS1 : KS0;
        const float* Vs_ = (kt&1) ? VS1 : VS0;

        // ---- S = Q K^T ----
        float c[16][4];
        #pragma unroll
        for (int j=0;j<16;j++){ c[j][0]=c[j][1]=c[j][2]=c[j][3]=0.f; }
        #pragma unroll
        for (int j=0;j<16;j++){
            #pragma unroll
            for (int kk=0;kk<8;kk++){
                unsigned b0=__float_as_uint(Ks_[(j*8+gid)*68 + kk*8   + l4]);
                unsigned b1=__float_as_uint(Ks_[(j*8+gid)*68 + kk*8+4 + l4]);
                MMA_TF32(c[j][0],c[j][1],c[j][2],c[j][3],
                         qf[kk][0],qf[kk][1],qf[kk][2],qf[kk][3],b0,b1);
            }
        }

        // ---- online softmax ----
        float mx_lo=-1e30f, mx_hi=-1e30f;
        #pragma unroll
        for (int j=0;j<16;j++){
            mx_lo = fmaxf(mx_lo, fmaxf(c[j][0], c[j][1]));
            mx_hi = fmaxf(mx_hi, fmaxf(c[j][2], c[j][3]));
        }
        mx_lo = fmaxf(mx_lo, __shfl_xor_sync(0xffffffffu, mx_lo, 1));
        mx_lo = fmaxf(mx_lo, __shfl_xor_sync(0xffffffffu, mx_lo, 2));
        mx_hi = fmaxf(mx_hi, __shfl_xor_sync(0xffffffffu, mx_hi, 1));
        mx_hi = fmaxf(mx_hi, __shfl_xor_sync(0xffffffffu, mx_hi, 2));
        float mn_lo = fmaxf(m_lo, mx_lo), mn_hi = fmaxf(m_hi, mx_hi);
        float al = __expf(m_lo - mn_lo), ah = __expf(m_hi - mn_hi);
        float s_lo=0.f, s_hi=0.f;
        #pragma unroll
        for (int j=0;j<16;j++){
            c[j][0]=__expf(c[j][0]-mn_lo); s_lo+=c[j][0];
            c[j][1]=__expf(c[j][1]-mn_lo); s_lo+=c[j][1];
            c[j][2]=__expf(c[j][2]-mn_hi); s_hi+=c[j][2];
            c[j][3]=__expf(c[j][3]-mn_hi); s_hi+=c[j][3];
        }
        s_lo += __shfl_xor_sync(0xffffffffu, s_lo, 1);
        s_lo += __shfl_xor_sync(0xffffffffu, s_lo, 2);
        s_hi += __shfl_xor_sync(0xffffffffu, s_hi, 1);
        s_hi += __shfl_xor_sync(0xffffffffu, s_hi, 2);
        l_lo = l_lo*al + s_lo;  l_hi = l_hi*ah + s_hi;
        m_lo = mn_lo;           m_hi = mn_hi;
        #pragma unroll
        for (int n=0;n<8;n++){
            o[n][0]*=al; o[n][1]*=al; o[n][2]*=ah; o[n][3]*=ah;
        }

        // ---- O += P V  (P A-frags via intra-quad shuffles) ----
        #pragma unroll
        for (int t=0;t<16;t++){
            float u0=__shfl_sync(0xffffffffu, c[t][0], src0);
            float u1=__shfl_sync(0xffffffffu, c[t][1], src0);
            float v0=__shfl_sync(0xffffffffu, c[t][2], src0);
            float v1=__shfl_sync(0xffffffffu, c[t][3], src0);
            float w0=__shfl_sync(0xffffffffu, c[t][0], src1);
            float w1=__shfl_sync(0xffffffffu, c[t][1], src1);
            float x0=__shfl_sync(0xffffffffu, c[t][2], src1);
            float x1=__shfl_sync(0xffffffffu, c[t][3], src1);
            unsigned a0 = tf32u(odd?u1:u0);
            unsigned a1 = tf32u(odd?v1:v0);
            unsigned a2 = tf32u(odd?w1:w0);
            unsigned a3 = tf32u(odd?x1:x0);
            #pragma unroll
            for (int n=0;n<8;n++){
                unsigned b0=__float_as_uint(Vs_[(t*8+l4  )*72 + n*8+gid]);
                unsigned b1=__float_as_uint(Vs_[(t*8+l4+4)*72 + n*8+gid]);
                MMA_TF32(o[n][0],o[n][1],o[n][2],o[n][3],a0,a1,a2,a3,b0,b1);
            }
        }
    }

    float il = 1.f/l_lo, ih = 1.f/l_hi;
    float* Op = g_o + base + qt*8192;
    const int r_lo = r0 + gid, r_hi = r_lo + 8;
    #pragma unroll
    for (int n=0;n<8;n++){
        int col = n*8 + 2*l4;
        *(float2*)(Op + r_lo*64 + col) = make_float2(o[n][0]*il, o[n][1]*il);
        *(float2*)(Op + r_hi*64 + col) = make_float2(o[n][2]*ih, o[n][3]*ih);
    }
}

// ==== Kernel E: out-proj GEMM [*,256]@[256,64] + residual + LN + transpose =
__global__ __launch_bounds__(256) void kE(const float* __restrict__ fc,
                                          const float* __restrict__ fcb,
                                          const float* __restrict__ lng,
                                          const float* __restrict__ lnb,
                                          float* __restrict__ out)
{
    __shared__ __align__(16) float As[64*68];
    __shared__ __align__(16) float Bs[64*68];
    float* Cs = Bs;
    const int stile = blockIdx.x, b = blockIdx.y, tid = threadIdx.x;
    const int tx = tid&15, ty = tid>>4;
    const int s0 = stile*64;

    float accv[4][4] = {};
    for (int h=0; h<4; h++){
        __syncthreads();
        const float* Ap = g_o + ((b*4+h)<<16) + s0*64;
        #pragma unroll
        for (int i=0;i<4;i++){
            int idx=i*256+tid, row=idx>>4, c4=(idx&15)*4;
            *(float4*)(As + row*68 + c4) = *(const float4*)(Ap + row*64 + c4);
            *(float4*)(Bs + row*68 + c4) = *(const float4*)(fc + (h*64+row)*64 + c4);
        }
        __syncthreads();
        #pragma unroll 8
        for (int k=0;k<64;k++){
            float a[4];
            #pragma unroll
            for (int i=0;i<4;i++) a[i] = As[(4*ty+i)*68 + k];
            float4 bb = *(const float4*)(Bs + k*68 + 4*tx);
            #pragma unroll
            for (int i=0;i<4;i++){
                accv[i][0] = fmaf(a[i], bb.x, accv[i][0]);
                accv[i][1] = fmaf(a[i], bb.y, accv[i][1]);
                accv[i][2] = fmaf(a[i], bb.z, accv[i][2]);
                accv[i][3] = fmaf(a[i], bb.w, accv[i][3]);
            }
        }
    }
    __syncthreads();
    #pragma unroll
    for (int i=0;i<4;i++){
        int r = 4*ty + i;
        #pragma unroll
        for (int j=0;j<4;j++){
            int c = 4*tx + j;
            Cs[r*68+c] = accv[i][j] + fcb[c] + g_cf[b*65536 + (s0+r)*64 + c];
        }
    }
    __syncthreads();
    {
        const int wid = tid>>5, lane = tid&31;
        for (int rr=0; rr<8; rr++){
            int r = wid*8 + rr;
            float v0 = Cs[r*68+lane], v1 = Cs[r*68+lane+32];
            float sm = v0+v1, sq = v0*v0 + v1*v1;
            #pragma unroll
            for (int off=16; off; off>>=1){
                sm += __shfl_xor_sync(0xffffffffu, sm, off);
                sq += __shfl_xor_sync(0xffffffffu, sq, off);
            }
            float mu = sm*(1.f/64.f);
            float var = sq*(1.f/64.f) - mu*mu;
            float rstd = rsqrtf(var + 1e-6f);
            Cs[r*68+lane]    = (v0-mu)*rstd*lng[lane]    + lnb[lane];
            Cs[r*68+lane+32] = (v1-mu)*rstd*lng[lane+32] + lnb[lane+32];
        }
    }
    __syncthreads();
    #pragma unroll
    for (int i=0;i<16;i++){
        int idx = i*256 + tid;
        int c = idx>>6, sl = idx&63;
        out[(((b<<6)+c)<<10) + s0 + sl] = Cs[sl*68+c];
    }
}

// ============================== launcher ===================================
extern "C" void kernel_launch(void* const* d_in, const int* in_sizes, int n_in,
                              void* d_out, int out_size)
{
    const float* x      = (const float*)d_in[0];
    const float* memory = (const float*)d_in[1];
    const float* wb_w   = (const float*)d_in[2];
    const float* wb_b   = (const float*)d_in[3];
    const float* a1_wq  = (const float*)d_in[4];
    const float* a1_bq  = (const float*)d_in[5];
    const float* a1_wk  = (const float*)d_in[6];
    const float* a1_bk  = (const float*)d_in[7];
    const float* a1_wv  = (const float*)d_in[8];
    const float* a1_bv  = (const float*)d_in[9];
    const float* a1_fc  = (const float*)d_in[10];
    const float* a1_fcb = (const float*)d_in[11];
    const float* a1_lng = (const float*)d_in[12];
    const float* a1_lnb = (const float*)d_in[13];
    const float* a2_wq  = (const float*)d_in[14];
    const float* a2_bq  = (const float*)d_in[15];
    const float* a2_wk  = (const float*)d_in[16];
    const float* a2_bk  = (const float*)d_in[17];
    const float* a2_wv  = (const float*)d_in[18];
    const float* a2_bv  = (const float*)d_in[19];
    const float* a2_fc  = (const float*)d_in[20];
    const float* a2_fcb = (const float*)d_in[21];
    const float* a2_lng = (const float*)d_in[22];
    const float* a2_lnb = (const float*)d_in[23];
    float* out = (float*)d_out;

    float *pq=0, *pk=0, *pv=0;
    cudaGetSymbolAddress((void**)&pq, g_q);
    cudaGetSymbolAddress((void**)&pk, g_k);
    cudaGetSymbolAddress((void**)&pv, g_v);

    const int kcm_smem = 17536*4;    // 70144 B
    const int kd_smem  = 35840*4;    // 143360 B
    cudaFuncSetAttribute(kCm, cudaFuncAttributeMaxDynamicSharedMemorySize, kcm_smem);
    cudaFuncSetAttribute(kD,  cudaFuncAttributeMaxDynamicSharedMemorySize, kd_smem);

    kA<<<NB, 1024>>>(x, wb_w, wb_b);
    kB<<<NB, 512>>>(x, memory, a1_wq, a1_bq, a1_wk, a1_bk, a1_wv, a1_bv,
                    a1_fc, a1_fcb, a1_lng, a1_lnb);
    dim3 gC(128, 2, 3);
    kCm<<<gC, 256, kcm_smem>>>(a2_wq, a2_wk, a2_wv, a2_bq, a2_bk, a2_bv, pq, pk, pv);
    dim3 gD(8, 4, NB);
    kD<<<gD, 256, kd_smem>>>();
    dim3 gE(16, NB);
    kE<<<gE, 256>>>(a2_fc, a2_fcb, a2_lng, a2_lnb, out);
}

// round 5
// speedup vs baseline: 4.1978x; 1.0170x over previous
#include <cuda_runtime.h>
#include <math.h>

#define NB   16
#define SEQ  1024
#define CH   64
#define NC   5
#define MD   96

// ---------------- scratch (device globals; no allocation) ----------------
__device__ float g_w1[NB*SEQ*NC];
__device__ float g_w2[NB*NC*SEQ];
__device__ float g_cf[NB*SEQ*CH];
__device__ float g_q [NB*4*SEQ*64];
__device__ float g_k [NB*4*SEQ*64];
__device__ float g_v [NB*4*SEQ*64];
__device__ float g_o [NB*4*SEQ*64];

// ---------------- helpers ----------------
__device__ __forceinline__ float tf32r(float x){
    unsigned u; asm("cvt.rna.tf32.f32 %0, %1;" : "=r"(u) : "f"(x));
    return __uint_as_float(u);
}
__device__ __forceinline__ unsigned tf32u(float x){
    unsigned u; asm("cvt.rna.tf32.f32 %0, %1;" : "=r"(u) : "f"(x));
    return u;
}
__device__ __forceinline__ void cp16(void* dst, const void* src){
    unsigned d = (unsigned)__cvta_generic_to_shared(dst);
    asm volatile("cp.async.cg.shared.global [%0], [%1], 16;" :: "r"(d), "l"(src));
}
#define CP_COMMIT asm volatile("cp.async.commit_group;")
#define CP_WAIT0  asm volatile("cp.async.wait_group 0;")
#define CP_WAIT1  asm volatile("cp.async.wait_group 1;")

#define MMA_TF32(c0,c1,c2,c3,a0,a1,a2,a3,b0,b1)                               \
  asm volatile("mma.sync.aligned.m16n8k8.row.col.f32.tf32.tf32.f32 "          \
    "{%0,%1,%2,%3}, {%4,%5,%6,%7}, {%8,%9}, {%0,%1,%2,%3};"                   \
    : "+f"(c0),"+f"(c1),"+f"(c2),"+f"(c3)                                     \
    : "r"(a0),"r"(a1),"r"(a2),"r"(a3),"r"(b0),"r"(b1))

// ================= Kernel A: weight = xt@wb_w, both softmaxes =============
__global__ __launch_bounds__(1024) void kA(const float* __restrict__ x,
                                           const float* __restrict__ wbw,
                                           const float* __restrict__ wbb)
{
    const int b = blockIdx.x, s = threadIdx.x;
    __shared__ float ws[CH*NC];
    __shared__ float red[32*NC];
    __shared__ float Mx[NC], Sx[NC];
    if (s < CH*NC) ws[s] = wbw[s];
    __syncthreads();

    const float* xb = x + b*(CH*SEQ) + s;
    float w[NC];
    #pragma unroll
    for (int n=0;n<NC;n++) w[n] = wbb[n];
    #pragma unroll 8
    for (int c=0;c<CH;c++){
        float xv = xb[c<<10];
        #pragma unroll
        for (int n=0;n<NC;n++) w[n] = fmaf(xv, ws[c*NC+n], w[n]);
    }

    {
        float mx = w[0];
        #pragma unroll
        for (int n=1;n<NC;n++) mx = fmaxf(mx, w[n]);
        float e[NC], ssum = 0.f;
        #pragma unroll
        for (int n=0;n<NC;n++){ e[n] = __expf(w[n]-mx); ssum += e[n]; }
        float inv = 1.f/ssum;
        float* w1p = g_w1 + b*(SEQ*NC) + s*NC;
        #pragma unroll
        for (int n=0;n<NC;n++) w1p[n] = e[n]*inv;
    }

    const int lane = s & 31, wid = s >> 5;
    float r5[NC];
    #pragma unroll
    for (int n=0;n<NC;n++) r5[n] = w[n];
    #pragma unroll
    for (int off=16; off; off>>=1)
        #pragma unroll
        for (int n=0;n<NC;n++) r5[n] = fmaxf(r5[n], __shfl_xor_sync(0xffffffffu, r5[n], off));
    if (lane==0){
        #pragma unroll
        for (int n=0;n<NC;n++) red[wid*NC+n] = r5[n];
    }
    __syncthreads();
    if (wid==0){
        #pragma unroll
        for (int n=0;n<NC;n++) r5[n] = red[lane*NC+n];
        #pragma unroll
        for (int off=16; off; off>>=1)
            #pragma unroll
            for (int n=0;n<NC;n++) r5[n] = fmaxf(r5[n], __shfl_xor_sync(0xffffffffu, r5[n], off));
        if (lane==0){
            #pragma unroll
            for (int n=0;n<NC;n++) Mx[n] = r5[n];
        }
    }
    __syncthreads();
    float e2[NC];
    #pragma unroll
    for (int n=0;n<NC;n++){ e2[n] = __expf(w[n]-Mx[n]); r5[n] = e2[n]; }
    #pragma unroll
    for (int off=16; off; off>>=1)
        #pragma unroll
        for (int n=0;n<NC;n++) r5[n] += __shfl_xor_sync(0xffffffffu, r5[n], off);
    if (lane==0){
        #pragma unroll
        for (int n=0;n<NC;n++) red[wid*NC+n] = r5[n];
    }
    __syncthreads();
    if (wid==0){
        #pragma unroll
        for (int n=0;n<NC;n++) r5[n] = red[lane*NC+n];
        #pragma unroll
        for (int off=16; off; off>>=1)
            #pragma unroll
            for (int n=0;n<NC;n++) r5[n] += __shfl_xor_sync(0xffffffffu, r5[n], off);
        if (lane==0){
            #pragma unroll
            for (int n=0;n<NC;n++) Sx[n] = r5[n];
        }
    }
    __syncthreads();
    float* w2p = g_w2 + b*(NC*SEQ) + s;
    #pragma unroll
    for (int n=0;n<NC;n++) w2p[n<<10] = e2[n] / Sx[n];
}

// ====== Kernel B: class pooling, MHA1 (5 tokens vs memory), redistribute ===
__global__ __launch_bounds__(512) void kB(const float* __restrict__ x,
    const float* __restrict__ memory,
    const float* __restrict__ wq, const float* __restrict__ bq,
    const float* __restrict__ wk, const float* __restrict__ bk,
    const float* __restrict__ wv, const float* __restrict__ bv,
    const float* __restrict__ fc, const float* __restrict__ fcb,
    const float* __restrict__ lng, const float* __restrict__ lnb)
{
    const int b = blockIdx.x, tid = threadIdx.x;
    __shared__ float xs[64*65];
    __shared__ float w2s[NC*64];
    __shared__ float cf1s[NC*64];
    __shared__ float mems[NC*MD];
    __shared__ float qh[NC*MD], kh[NC*MD], vh[NC*64];
    __shared__ float Ssm[NC*NC];
    __shared__ float osm[NC*64];
    __shared__ float projs[NC*64];

    float acc = 0.f;
    for (int st=0; st<16; st++){
        __syncthreads();
        const int s0 = st*64;
        #pragma unroll
        for (int i=0;i<8;i++){
            int idx = i*512 + tid;
            int c = idx>>6, sl = idx&63;
            xs[c*65+sl] = x[b*65536 + (c<<10) + s0 + sl];
        }
        if (tid < 320)
            w2s[tid] = g_w2[b*5120 + ((tid>>6)<<10) + s0 + (tid&63)];
        __syncthreads();
        if (tid < 320){
            const int n = tid>>6, c = tid&63;
            float a = 0.f;
            #pragma unroll 8
            for (int sl=0; sl<64; sl++) a = fmaf(w2s[n*64+sl], xs[c*65+sl], a);
            acc += a;
        }
    }
    if (tid < 320) cf1s[tid] = acc;
    if (tid < NC*MD) mems[tid] = memory[tid];
    __syncthreads();

    if (tid < 480){
        const int n = tid/96, j = tid - n*96;
        float q = bq[j];
        #pragma unroll
        for (int d=0; d<64; d++) q = fmaf(cf1s[n*64+d], wq[d*96+j], q);
        qh[tid] = q * 0.102062072615966f;
        float kk = bk[j];
        #pragma unroll
        for (int d=0; d<96; d++) kk = fmaf(mems[n*96+d], wk[d*96+j], kk);
        kh[tid] = kk;
    }
    if (tid < 320){
        const int n = tid>>6, c = tid&63;
        float vv = bv[c];
        #pragma unroll
        for (int d=0; d<96; d++) vv = fmaf(mems[n*96+d], wv[d*64+c], vv);
        vh[tid] = vv;
    }
    __syncthreads();

    if (tid < 25){
        const int i = tid/5, j = tid - (tid/5)*5;
        float sv = 0.f;
        #pragma unroll
        for (int d=0; d<96; d++) sv = fmaf(qh[i*96+d], kh[j*96+d], sv);
        Ssm[tid] = sv;
    }
    __syncthreads();
    if (tid < 5){
        float m = Ssm[tid*5];
        #pragma unroll
        for (int j=1;j<5;j++) m = fmaxf(m, Ssm[tid*5+j]);
        float p[5], sum = 0.f;
        #pragma unroll
        for (int j=0;j<5;j++){ p[j] = __expf(Ssm[tid*5+j]-m); sum += p[j]; }
        float inv = 1.f/sum;
        #pragma unroll
        for (int j=0;j<5;j++) Ssm[tid*5+j] = p[j]*inv;
    }
    __syncthreads();
    if (tid < 320){
        const int n = tid>>6, c = tid&63;
        float o = 0.f;
        #pragma unroll
        for (int j=0;j<5;j++) o = fmaf(Ssm[n*5+j], vh[j*64+c], o);
        osm[tid] = o;
    }
    __syncthreads();
    if (tid < 320){
        const int n = tid>>6, c = tid&63;
        float p = fcb[c] + cf1s[tid];
        #pragma unroll
        for (int k=0;k<64;k++) p = fmaf(osm[n*64+k], fc[k*64+c], p);
        projs[tid] = p;
    }
    __syncthreads();
    if (tid < 160){
        const int n = tid>>5, lane = tid&31;
        float v0 = projs[n*64+lane], v1 = projs[n*64+lane+32];
        float sm = v0+v1, sq = v0*v0 + v1*v1;
        #pragma unroll
        for (int off=16; off; off>>=1){
            sm += __shfl_xor_sync(0xffffffffu, sm, off);
            sq += __shfl_xor_sync(0xffffffffu, sq, off);
        }
        float mu = sm*(1.f/64.f);
        float var = sq*(1.f/64.f) - mu*mu;
        float rs = rsqrtf(var + 1e-6f);
        cf1s[n*64+lane]    = (v0-mu)*rs*lng[lane]    + lnb[lane];
        cf1s[n*64+lane+32] = (v1-mu)*rs*lng[lane+32] + lnb[lane+32];
    }
    __syncthreads();
    for (int it=0; it<128; it++){
        int idx = it*512 + tid;
        int s = idx>>6, c = idx&63;
        const float* w1p = g_w1 + b*5120 + s*5;
        float a = 0.f;
        #pragma unroll
        for (int n=0;n<5;n++) a = fmaf(w1p[n], cf1s[n*64+c], a);
        g_cf[b*65536 + idx] = a;
    }
}

// ====== Kernel Cm: fused QKV projection via tf32 mma ======================
__global__ __launch_bounds__(256) void kCm(
    const float* __restrict__ wq, const float* __restrict__ wk, const float* __restrict__ wv,
    const float* __restrict__ bq, const float* __restrict__ bk, const float* __restrict__ bv,
    float* __restrict__ pq, float* __restrict__ pk, float* __restrict__ pv)
{
    extern __shared__ float smc[];
    float* Ast = smc;          // [128][68]
    float* Ws  = smc + 8704;   // [64][136]
    float* bs  = smc + 17408;  // [128]
    const int mt=blockIdx.x, nt=blockIdx.y, z=blockIdx.z;
    const int tid=threadIdx.x, w=tid>>5, lane=tid&31, gid=lane>>2, l4=lane&3;
    const float* W  = (z==0)?wq:((z==1)?wk:wv);
    const float* Bp = (z==0)?bq:((z==1)?bk:bv);
    float*       O  = (z==0)?pq:((z==1)?pk:pv);

    const float* Ap = g_cf + mt*128*64;
    #pragma unroll
    for (int i=0;i<8;i++){
        int idx=i*256+tid, row=idx>>4, c4=(idx&15)*4;
        *(float4*)(Ast + row*68 + c4) = *(const float4*)(Ap + row*64 + c4);
    }
    #pragma unroll
    for (int i=0;i<8;i++){
        int idx=i*256+tid, row=idx>>5, c4=(idx&31)*4;
        *(float4*)(Ws + row*136 + c4) = *(const float4*)(W + row*256 + nt*128 + c4);
    }
    if (tid<128) bs[tid] = Bp[nt*128+tid];
    __syncthreads();

    unsigned af[8][4];
    const int r0 = w*16;
    #pragma unroll
    for (int kk=0;kk<8;kk++){
        af[kk][0]=__float_as_uint(Ast[(r0+gid  )*68 + kk*8   + l4]);
        af[kk][1]=__float_as_uint(Ast[(r0+gid+8)*68 + kk*8   + l4]);
        af[kk][2]=__float_as_uint(Ast[(r0+gid  )*68 + kk*8+4 + l4]);
        af[kk][3]=__float_as_uint(Ast[(r0+gid+8)*68 + kk*8+4 + l4]);
    }
    float c[16][4];
    #pragma unroll
    for (int j=0;j<16;j++){ c[j][0]=c[j][1]=c[j][2]=c[j][3]=0.f; }
    #pragma unroll
    for (int j=0;j<16;j++){
        #pragma unroll
        for (int kk=0;kk<8;kk++){
            unsigned b0=__float_as_uint(Ws[(kk*8+l4  )*136 + j*8+gid]);
            unsigned b1=__float_as_uint(Ws[(kk*8+l4+4)*136 + j*8+gid]);
            MMA_TF32(c[j][0],c[j][1],c[j][2],c[j][3],
                     af[kk][0],af[kk][1],af[kk][2],af[kk][3],b0,b1);
        }
    }
    const int row_lo = mt*128 + r0 + gid;
    const int bidx = row_lo>>10, s_lo = row_lo&1023;
    #pragma unroll
    for (int j=0;j<16;j++){
        int cl = j*8 + 2*l4;
        int col = nt*128 + cl;
        int h = col>>6, d = col&63;
        float* op = O + (((bidx<<2)+h)<<16);
        float2 vlo = make_float2(tf32r(c[j][0]+bs[cl]), tf32r(c[j][1]+bs[cl+1]));
        float2 vhi = make_float2(tf32r(c[j][2]+bs[cl]), tf32r(c[j][3]+bs[cl+1]));
        *(float2*)(op + s_lo*64 + d)     = vlo;
        *(float2*)(op + (s_lo+8)*64 + d) = vhi;
    }
}

// ========== Kernel D: tf32 mma flash attention (2 CTAs/SM) ================
// CTA: 256 thr / 8 warps, 128 q-rows; K/V tiles 64 rows, double-buffered
// depth-2 cp.async. smem = 71,680 B -> 2 CTAs/SM; regs capped at 128.
__global__ __launch_bounds__(256, 2) void kD()
{
    extern __shared__ float sm[];
    float* KS0 = sm;             // [64][68]
    float* VS0 = sm + 4352;      // [64][72]
    float* KS1 = sm + 8960;      // [64][68]
    float* VS1 = sm + 13312;     // [64][72]
    float* Qst = sm;             // alias [128][68] (used before K/V loads)

    const int qt=blockIdx.x, h=blockIdx.y, b=blockIdx.z;
    const int tid=threadIdx.x, w=tid>>5, lane=tid&31;
    const int gid=lane>>2, l4=lane&3;
    const int base=((b*4+h)<<16);

    const float* Kg = g_k + base;
    const float* Vg = g_v + base;
    const float* Qg = g_q + base + qt*8192;

    // stage Q (scaled by 1/sqrt(64)); g_q already tf32-rounded
    #pragma unroll
    for (int i=0;i<8;i++){
        int idx=i*256+tid, row=idx>>4, c4=(idx&15)*4;
        float4 v = *(const float4*)(Qg + row*64 + c4);
        Qst[row*68+c4+0]=v.x*0.125f; Qst[row*68+c4+1]=v.y*0.125f;
        Qst[row*68+c4+2]=v.z*0.125f; Qst[row*68+c4+3]=v.w*0.125f;
    }
    __syncthreads();
    unsigned qf[8][4];
    const int r0 = w*16;
    #pragma unroll
    for (int kk=0;kk<8;kk++){
        qf[kk][0]=__float_as_uint(Qst[(r0+gid  )*68 + kk*8   + l4]);
        qf[kk][1]=__float_as_uint(Qst[(r0+gid+8)*68 + kk*8   + l4]);
        qf[kk][2]=__float_as_uint(Qst[(r0+gid  )*68 + kk*8+4 + l4]);
        qf[kk][3]=__float_as_uint(Qst[(r0+gid+8)*68 + kk*8+4 + l4]);
    }
    __syncthreads();   // done reading Qst before K/V overwrite

    // prefetch tiles 0 and 1 (one group each; 64x64 fp32 = 1024 float4/tile)
    #pragma unroll
    for (int i=0;i<4;i++){
        int idx=i*256+tid, row=idx>>4, c4=(idx&15)*4;
        cp16(KS0 + row*68 + c4, Kg + row*64 + c4);
        cp16(VS0 + row*72 + c4, Vg + row*64 + c4);
    }
    CP_COMMIT;
    #pragma unroll
    for (int i=0;i<4;i++){
        int idx=i*256+tid, row=idx>>4, c4=(idx&15)*4;
        cp16(KS1 + row*68 + c4, Kg + 4096 + row*64 + c4);
        cp16(VS1 + row*72 + c4, Vg + 4096 + row*64 + c4);
    }
    CP_COMMIT;

    float o[8][4];
    #pragma unroll
    for (int n=0;n<8;n++){ o[n][0]=o[n][1]=o[n][2]=o[n][3]=0.f; }
    float m_lo=-1e30f, m_hi=-1e30f, l_lo=0.f, l_hi=0.f;

    for (int kt=0; kt<16; kt++){
        CP_WAIT1;          // oldest outstanding group (tile kt) complete
        __syncthreads();
        const float* Ks_ = (kt&1) ? KS1 : KS0;
        const float* Vs_ = (kt&1) ? VS1 : VS0;

        // ---- S = Q K^T  (16x64 per warp) ----
        float c[8][4];
        #pragma unroll
        for (int j=0;j<8;j++){ c[j][0]=c[j][1]=c[j][2]=c[j][3]=0.f; }
        #pragma unroll
        for (int j=0;j<8;j++){
            #pragma unroll
            for (int kk=0;kk<8;kk++){
                unsigned b0=__float_as_uint(Ks_[(j*8+gid)*68 + kk*8   + l4]);
                unsigned b1=__float_as_uint(Ks_[(j*8+gid)*68 + kk*8+4 + l4]);
                MMA_TF32(c[j][0],c[j][1],c[j][2],c[j][3],
                         qf[kk][0],qf[kk][1],qf[kk][2],qf[kk][3],b0,b1);
            }
        }

        // ---- online softmax ----
        float mx_lo=-1e30f, mx_hi=-1e30f;
        #pragma unroll
        for (int j=0;j<8;j++){
            mx_lo = fmaxf(mx_lo, fmaxf(c[j][0], c[j][1]));
            mx_hi = fmaxf(mx_hi, fmaxf(c[j][2], c[j][3]));
        }
        mx_lo = fmaxf(mx_lo, __shfl_xor_sync(0xffffffffu, mx_lo, 1));
        mx_lo = fmaxf(mx_lo, __shfl_xor_sync(0xffffffffu, mx_lo, 2));
        mx_hi = fmaxf(mx_hi, __shfl_xor_sync(0xffffffffu, mx_hi, 1));
        mx_hi = fmaxf(mx_hi, __shfl_xor_sync(0xffffffffu, mx_hi, 2));
        float mn_lo = fmaxf(m_lo, mx_lo), mn_hi = fmaxf(m_hi, mx_hi);
        float al = __expf(m_lo - mn_lo), ah = __expf(m_hi - mn_hi);
        float s_lo=0.f, s_hi=0.f;
        #pragma unroll
        for (int j=0;j<8;j++){
            c[j][0]=__expf(c[j][0]-mn_lo); s_lo+=c[j][0];
            c[j][1]=__expf(c[j][1]-mn_lo); s_lo+=c[j][1];
            c[j][2]=__expf(c[j][2]-mn_hi); s_hi+=c[j][2];
            c[j][3]=__expf(c[j][3]-mn_hi); s_hi+=c[j][3];
        }
        s_lo += __shfl_xor_sync(0xffffffffu, s_lo, 1);
        s_lo += __shfl_xor_sync(0xffffffffu, s_lo, 2);
        s_hi += __shfl_xor_sync(0xffffffffu, s_hi, 1);
        s_hi += __shfl_xor_sync(0xffffffffu, s_hi, 2);
        l_lo = l_lo*al + s_lo;  l_hi = l_hi*ah + s_hi;
        m_lo = mn_lo;           m_hi = mn_hi;
        #pragma unroll
        for (int n=0;n<8;n++){
            o[n][0]*=al; o[n][1]*=al; o[n][2]*=ah; o[n][3]*=ah;
        }

        // ---- O += P V  (P A-frags via intra-quad shuffles) ----
        {
            const int src0 = (lane & ~3) | (l4>>1);
            const int src1 = src0 | 2;
            const bool odd = (l4&1);
            #pragma unroll
            for (int t=0;t<8;t++){
                float u0=__shfl_sync(0xffffffffu, c[t][0], src0);
                float u1=__shfl_sync(0xffffffffu, c[t][1], src0);
                float v0=__shfl_sync(0xffffffffu, c[t][2], src0);
                float v1=__shfl_sync(0xffffffffu, c[t][3], src0);
                float w0=__shfl_sync(0xffffffffu, c[t][0], src1);
                float w1=__shfl_sync(0xffffffffu, c[t][1], src1);
                float x0=__shfl_sync(0xffffffffu, c[t][2], src1);
                float x1=__shfl_sync(0xffffffffu, c[t][3], src1);
                unsigned a0 = tf32u(odd?u1:u0);
                unsigned a1 = tf32u(odd?v1:v0);
                unsigned a2 = tf32u(odd?w1:w0);
                unsigned a3 = tf32u(odd?x1:x0);
                #pragma unroll
                for (int n=0;n<8;n++){
                    unsigned b0=__float_as_uint(Vs_[(t*8+l4  )*72 + n*8+gid]);
                    unsigned b1=__float_as_uint(Vs_[(t*8+l4+4)*72 + n*8+gid]);
                    MMA_TF32(o[n][0],o[n][1],o[n][2],o[n][3],a0,a1,a2,a3,b0,b1);
                }
            }
        }

        __syncthreads();   // all warps done with buf[kt&1]
        if (kt < 14){
            const float* Kp = Kg + (kt+2)*4096;
            const float* Vp = Vg + (kt+2)*4096;
            float* kd = (kt&1) ? KS1 : KS0;
            float* vd = (kt&1) ? VS1 : VS0;
            #pragma unroll
            for (int i=0;i<4;i++){
                int idx=i*256+tid, row=idx>>4, c4=(idx&15)*4;
                cp16(kd + row*68 + c4, Kp + row*64 + c4);
                cp16(vd + row*72 + c4, Vp + row*64 + c4);
            }
        }
        CP_COMMIT;   // empty group when kt>=14 keeps group accounting uniform
    }

    float il = 1.f/l_lo, ih = 1.f/l_hi;
    float* Op = g_o + base + qt*8192;
    const int r_lo = r0 + gid, r_hi = r_lo + 8;
    #pragma unroll
    for (int n=0;n<8;n++){
        int col = n*8 + 2*l4;
        *(float2*)(Op + r_lo*64 + col) = make_float2(o[n][0]*il, o[n][1]*il);
        *(float2*)(Op + r_hi*64 + col) = make_float2(o[n][2]*ih, o[n][3]*ih);
    }
}

// ==== Kernel E: out-proj GEMM [*,256]@[256,64] + residual + LN + transpose =
__global__ __launch_bounds__(256) void kE(const float* __restrict__ fc,
                                          const float* __restrict__ fcb,
                                          const float* __restrict__ lng,
                                          const float* __restrict__ lnb,
                                          float* __restrict__ out)
{
    __shared__ __align__(16) float As[64*68];
    __shared__ __align__(16) float Bs[64*68];
    float* Cs = Bs;
    const int stile = blockIdx.x, b = blockIdx.y, tid = threadIdx.x;
    const int tx = tid&15, ty = tid>>4;
    const int s0 = stile*64;

    float accv[4][4] = {};
    for (int h=0; h<4; h++){
        __syncthreads();
        const float* Ap = g_o + ((b*4+h)<<16) + s0*64;
        #pragma unroll
        for (int i=0;i<4;i++){
            int idx=i*256+tid, row=idx>>4, c4=(idx&15)*4;
            *(float4*)(As + row*68 + c4) = *(const float4*)(Ap + row*64 + c4);
            *(float4*)(Bs + row*68 + c4) = *(const float4*)(fc + (h*64+row)*64 + c4);
        }
        __syncthreads();
        #pragma unroll 8
        for (int k=0;k<64;k++){
            float a[4];
            #pragma unroll
            for (int i=0;i<4;i++) a[i] = As[(4*ty+i)*68 + k];
            float4 bb = *(const float4*)(Bs + k*68 + 4*tx);
            #pragma unroll
            for (int i=0;i<4;i++){
                accv[i][0] = fmaf(a[i], bb.x, accv[i][0]);
                accv[i][1] = fmaf(a[i], bb.y, accv[i][1]);
                accv[i][2] = fmaf(a[i], bb.z, accv[i][2]);
                accv[i][3] = fmaf(a[i], bb.w, accv[i][3]);
            }
        }
    }
    __syncthreads();
    #pragma unroll
    for (int i=0;i<4;i++){
        int r = 4*ty + i;
        #pragma unroll
        for (int j=0;j<4;j++){
            int c = 4*tx + j;
            Cs[r*68+c] = accv[i][j] + fcb[c] + g_cf[b*65536 + (s0+r)*64 + c];
        }
    }
    __syncthreads();
    {
        const int wid = tid>>5, lane = tid&31;
        for (int rr=0; rr<8; rr++){
            int r = wid*8 + rr;
            float v0 = Cs[r*68+lane], v1 = Cs[r*68+lane+32];
            float sm = v0+v1, sq = v0*v0 + v1*v1;
            #pragma unroll
            for (int off=16; off; off>>=1){
                sm += __shfl_xor_sync(0xffffffffu, sm, off);
                sq += __shfl_xor_sync(0xffffffffu, sq, off);
            }
            float mu = sm*(1.f/64.f);
            float var = sq*(1.f/64.f) - mu*mu;
            float rstd = rsqrtf(var + 1e-6f);
            Cs[r*68+lane]    = (v0-mu)*rstd*lng[lane]    + lnb[lane];
            Cs[r*68+lane+32] = (v1-mu)*rstd*lng[lane+32] + lnb[lane+32];
        }
    }
    __syncthreads();
    #pragma unroll
    for (int i=0;i<16;i++){
        int idx = i*256 + tid;
        int c = idx>>6, sl = idx&63;
        out[(((b<<6)+c)<<10) + s0 + sl] = Cs[sl*68+c];
    }
}

// ============================== launcher ===================================
extern "C" void kernel_launch(void* const* d_in, const int* in_sizes, int n_in,
                              void* d_out, int out_size)
{
    const float* x      = (const float*)d_in[0];
    const float* memory = (const float*)d_in[1];
    const float* wb_w   = (const float*)d_in[2];
    const float* wb_b   = (const float*)d_in[3];
    const float* a1_wq  = (const float*)d_in[4];
    const float* a1_bq  = (const float*)d_in[5];
    const float* a1_wk  = (const float*)d_in[6];
    const float* a1_bk  = (const float*)d_in[7];
    const float* a1_wv  = (const float*)d_in[8];
    const float* a1_bv  = (const float*)d_in[9];
    const float* a1_fc  = (const float*)d_in[10];
    const float* a1_fcb = (const float*)d_in[11];
    const float* a1_lng = (const float*)d_in[12];
    const float* a1_lnb = (const float*)d_in[13];
    const float* a2_wq  = (const float*)d_in[14];
    const float* a2_bq  = (const float*)d_in[15];
    const float* a2_wk  = (const float*)d_in[16];
    const float* a2_bk  = (const float*)d_in[17];
    const float* a2_wv  = (const float*)d_in[18];
    const float* a2_bv  = (const float*)d_in[19];
    const float* a2_fc  = (const float*)d_in[20];
    const float* a2_fcb = (const float*)d_in[21];
    const float* a2_lng = (const float*)d_in[22];
    const float* a2_lnb = (const float*)d_in[23];
    float* out = (float*)d_out;

    float *pq=0, *pk=0, *pv=0;
    cudaGetSymbolAddress((void**)&pq, g_q);
    cudaGetSymbolAddress((void**)&pk, g_k);
    cudaGetSymbolAddress((void**)&pv, g_v);

    const int kcm_smem = 17536*4;    // 70144 B
    const int kd_smem  = 17920*4;    // 71680 B -> 2 CTAs/SM
    cudaFuncSetAttribute(kCm, cudaFuncAttributeMaxDynamicSharedMemorySize, kcm_smem);
    cudaFuncSetAttribute(kD,  cudaFuncAttributeMaxDynamicSharedMemorySize, kd_smem);

    kA<<<NB, 1024>>>(x, wb_w, wb_b);
    kB<<<NB, 512>>>(x, memory, a1_wq, a1_bq, a1_wk, a1_bk, a1_wv, a1_bv,
                    a1_fc, a1_fcb, a1_lng, a1_lnb);
    dim3 gC(128, 2, 3);
    kCm<<<gC, 256, kcm_smem>>>(a2_wq, a2_wk, a2_wv, a2_bq, a2_bk, a2_bv, pq, pk, pv);
    dim3 gD(8, 4, NB);
    kD<<<gD, 256, kd_smem>>>();
    dim3 gE(16, NB);
    kE<<<gE, 256>>>(a2_fc, a2_fcb, a2_lng, a2_lnb, out);
}

// round 6
// speedup vs baseline: 4.6231x; 1.1013x over previous
#include <cuda_runtime.h>
#include <math.h>

#define NB   16
#define SEQ  1024
#define CH   64
#define NC   5
#define MD   96

// ---------------- scratch (device globals; no allocation) ----------------
__device__ float g_w1[NB*SEQ*NC];
__device__ float g_w2[NB*NC*SEQ];
__device__ float g_cf[NB*SEQ*CH];
__device__ float g_q [NB*4*SEQ*64];   // [b][h][s][d']  (d pair-interleaved)
__device__ float g_k [NB*4*SEQ*64];   // [b][h][s][d']  (d pair-interleaved)
__device__ float g_v [NB*4*SEQ*64];   // [b][h][d][s]   (TRANSPOSED)
__device__ float g_o [NB*4*SEQ*64];

// ---------------- helpers ----------------
__device__ __forceinline__ float tf32r(float x){
    unsigned u; asm("cvt.rna.tf32.f32 %0, %1;" : "=r"(u) : "f"(x));
    return __uint_as_float(u);
}
__device__ __forceinline__ unsigned tf32u(float x){
    unsigned u; asm("cvt.rna.tf32.f32 %0, %1;" : "=r"(u) : "f"(x));
    return u;
}
__device__ __forceinline__ void cp16(void* dst, const void* src){
    unsigned d = (unsigned)__cvta_generic_to_shared(dst);
    asm volatile("cp.async.cg.shared.global [%0], [%1], 16;" :: "r"(d), "l"(src));
}
#define CP_COMMIT asm volatile("cp.async.commit_group;")
#define CP_WAIT1  asm volatile("cp.async.wait_group 1;")

#define MMA_TF32(c0,c1,c2,c3,a0,a1,a2,a3,b0,b1)                               \
  asm volatile("mma.sync.aligned.m16n8k8.row.col.f32.tf32.tf32.f32 "          \
    "{%0,%1,%2,%3}, {%4,%5,%6,%7}, {%8,%9}, {%0,%1,%2,%3};"                   \
    : "+f"(c0),"+f"(c1),"+f"(c2),"+f"(c3)                                     \
    : "r"(a0),"r"(a1),"r"(a2),"r"(a3),"r"(b0),"r"(b1))

// ================= Kernel A: weight = xt@wb_w, both softmaxes =============
__global__ __launch_bounds__(1024) void kA(const float* __restrict__ x,
                                           const float* __restrict__ wbw,
                                           const float* __restrict__ wbb)
{
    const int b = blockIdx.x, s = threadIdx.x;
    __shared__ float ws[CH*NC];
    __shared__ float red[32*NC];
    __shared__ float Mx[NC], Sx[NC];
    if (s < CH*NC) ws[s] = wbw[s];
    __syncthreads();

    const float* xb = x + b*(CH*SEQ) + s;
    float w[NC];
    #pragma unroll
    for (int n=0;n<NC;n++) w[n] = wbb[n];
    #pragma unroll 8
    for (int c=0;c<CH;c++){
        float xv = xb[c<<10];
        #pragma unroll
        for (int n=0;n<NC;n++) w[n] = fmaf(xv, ws[c*NC+n], w[n]);
    }

    {
        float mx = w[0];
        #pragma unroll
        for (int n=1;n<NC;n++) mx = fmaxf(mx, w[n]);
        float e[NC], ssum = 0.f;
        #pragma unroll
        for (int n=0;n<NC;n++){ e[n] = __expf(w[n]-mx); ssum += e[n]; }
        float inv = 1.f/ssum;
        float* w1p = g_w1 + b*(SEQ*NC) + s*NC;
        #pragma unroll
        for (int n=0;n<NC;n++) w1p[n] = e[n]*inv;
    }

    const int lane = s & 31, wid = s >> 5;
    float r5[NC];
    #pragma unroll
    for (int n=0;n<NC;n++) r5[n] = w[n];
    #pragma unroll
    for (int off=16; off; off>>=1)
        #pragma unroll
        for (int n=0;n<NC;n++) r5[n] = fmaxf(r5[n], __shfl_xor_sync(0xffffffffu, r5[n], off));
    if (lane==0){
        #pragma unroll
        for (int n=0;n<NC;n++) red[wid*NC+n] = r5[n];
    }
    __syncthreads();
    if (wid==0){
        #pragma unroll
        for (int n=0;n<NC;n++) r5[n] = red[lane*NC+n];
        #pragma unroll
        for (int off=16; off; off>>=1)
            #pragma unroll
            for (int n=0;n<NC;n++) r5[n] = fmaxf(r5[n], __shfl_xor_sync(0xffffffffu, r5[n], off));
        if (lane==0){
            #pragma unroll
            for (int n=0;n<NC;n++) Mx[n] = r5[n];
        }
    }
    __syncthreads();
    float e2[NC];
    #pragma unroll
    for (int n=0;n<NC;n++){ e2[n] = __expf(w[n]-Mx[n]); r5[n] = e2[n]; }
    #pragma unroll
    for (int off=16; off; off>>=1)
        #pragma unroll
        for (int n=0;n<NC;n++) r5[n] += __shfl_xor_sync(0xffffffffu, r5[n], off);
    if (lane==0){
        #pragma unroll
        for (int n=0;n<NC;n++) red[wid*NC+n] = r5[n];
    }
    __syncthreads();
    if (wid==0){
        #pragma unroll
        for (int n=0;n<NC;n++) r5[n] = red[lane*NC+n];
        #pragma unroll
        for (int off=16; off; off>>=1)
            #pragma unroll
            for (int n=0;n<NC;n++) r5[n] += __shfl_xor_sync(0xffffffffu, r5[n], off);
        if (lane==0){
            #pragma unroll
            for (int n=0;n<NC;n++) Sx[n] = r5[n];
        }
    }
    __syncthreads();
    float* w2p = g_w2 + b*(NC*SEQ) + s;
    #pragma unroll
    for (int n=0;n<NC;n++) w2p[n<<10] = e2[n] / Sx[n];
}

// ====== Kernel B: class pooling, MHA1 (5 tokens vs memory), redistribute ===
__global__ __launch_bounds__(512) void kB(const float* __restrict__ x,
    const float* __restrict__ memory,
    const float* __restrict__ wq, const float* __restrict__ bq,
    const float* __restrict__ wk, const float* __restrict__ bk,
    const float* __restrict__ wv, const float* __restrict__ bv,
    const float* __restrict__ fc, const float* __restrict__ fcb,
    const float* __restrict__ lng, const float* __restrict__ lnb)
{
    const int b = blockIdx.x, tid = threadIdx.x;
    __shared__ float xs[64*65];
    __shared__ float w2s[NC*64];
    __shared__ float cf1s[NC*64];
    __shared__ float mems[NC*MD];
    __shared__ float qh[NC*MD], kh[NC*MD], vh[NC*64];
    __shared__ float Ssm[NC*NC];
    __shared__ float osm[NC*64];
    __shared__ float projs[NC*64];

    float acc = 0.f;
    for (int st=0; st<16; st++){
        __syncthreads();
        const int s0 = st*64;
        #pragma unroll
        for (int i=0;i<8;i++){
            int idx = i*512 + tid;
            int c = idx>>6, sl = idx&63;
            xs[c*65+sl] = x[b*65536 + (c<<10) + s0 + sl];
        }
        if (tid < 320)
            w2s[tid] = g_w2[b*5120 + ((tid>>6)<<10) + s0 + (tid&63)];
        __syncthreads();
        if (tid < 320){
            const int n = tid>>6, c = tid&63;
            float a = 0.f;
            #pragma unroll 8
            for (int sl=0; sl<64; sl++) a = fmaf(w2s[n*64+sl], xs[c*65+sl], a);
            acc += a;
        }
    }
    if (tid < 320) cf1s[tid] = acc;
    if (tid < NC*MD) mems[tid] = memory[tid];
    __syncthreads();

    if (tid < 480){
        const int n = tid/96, j = tid - n*96;
        float q = bq[j];
        #pragma unroll
        for (int d=0; d<64; d++) q = fmaf(cf1s[n*64+d], wq[d*96+j], q);
        qh[tid] = q * 0.102062072615966f;
        float kk = bk[j];
        #pragma unroll
        for (int d=0; d<96; d++) kk = fmaf(mems[n*96+d], wk[d*96+j], kk);
        kh[tid] = kk;
    }
    if (tid < 320){
        const int n = tid>>6, c = tid&63;
        float vv = bv[c];
        #pragma unroll
        for (int d=0; d<96; d++) vv = fmaf(mems[n*96+d], wv[d*64+c], vv);
        vh[tid] = vv;
    }
    __syncthreads();

    if (tid < 25){
        const int i = tid/5, j = tid - (tid/5)*5;
        float sv = 0.f;
        #pragma unroll
        for (int d=0; d<96; d++) sv = fmaf(qh[i*96+d], kh[j*96+d], sv);
        Ssm[tid] = sv;
    }
    __syncthreads();
    if (tid < 5){
        float m = Ssm[tid*5];
        #pragma unroll
        for (int j=1;j<5;j++) m = fmaxf(m, Ssm[tid*5+j]);
        float p[5], sum = 0.f;
        #pragma unroll
        for (int j=0;j<5;j++){ p[j] = __expf(Ssm[tid*5+j]-m); sum += p[j]; }
        float inv = 1.f/sum;
        #pragma unroll
        for (int j=0;j<5;j++) Ssm[tid*5+j] = p[j]*inv;
    }
    __syncthreads();
    if (tid < 320){
        const int n = tid>>6, c = tid&63;
        float o = 0.f;
        #pragma unroll
        for (int j=0;j<5;j++) o = fmaf(Ssm[n*5+j], vh[j*64+c], o);
        osm[tid] = o;
    }
    __syncthreads();
    if (tid < 320){
        const int n = tid>>6, c = tid&63;
        float p = fcb[c] + cf1s[tid];
        #pragma unroll
        for (int k=0;k<64;k++) p = fmaf(osm[n*64+k], fc[k*64+c], p);
        projs[tid] = p;
    }
    __syncthreads();
    if (tid < 160){
        const int n = tid>>5, lane = tid&31;
        float v0 = projs[n*64+lane], v1 = projs[n*64+lane+32];
        float sm = v0+v1, sq = v0*v0 + v1*v1;
        #pragma unroll
        for (int off=16; off; off>>=1){
            sm += __shfl_xor_sync(0xffffffffu, sm, off);
            sq += __shfl_xor_sync(0xffffffffu, sq, off);
        }
        float mu = sm*(1.f/64.f);
        float var = sq*(1.f/64.f) - mu*mu;
        float rs = rsqrtf(var + 1e-6f);
        cf1s[n*64+lane]    = (v0-mu)*rs*lng[lane]    + lnb[lane];
        cf1s[n*64+lane+32] = (v1-mu)*rs*lng[lane+32] + lnb[lane+32];
    }
    __syncthreads();
    for (int it=0; it<128; it++){
        int idx = it*512 + tid;
        int s = idx>>6, c = idx&63;
        const float* w1p = g_w1 + b*5120 + s*5;
        float a = 0.f;
        #pragma unroll
        for (int n=0;n<5;n++) a = fmaf(w1p[n], cf1s[n*64+c], a);
        g_cf[b*65536 + idx] = a;
    }
}

// ====== Kernel Cm: fused QKV projection via tf32 mma ======================
// z<2 (Q,K): store with d pair-interleaved within each group of 8.
// z==2 (V):  store transposed [d][s].
__global__ __launch_bounds__(256) void kCm(
    const float* __restrict__ wq, const float* __restrict__ wk, const float* __restrict__ wv,
    const float* __restrict__ bq, const float* __restrict__ bk, const float* __restrict__ bv,
    float* __restrict__ pq, float* __restrict__ pk, float* __restrict__ pv)
{
    extern __shared__ float smc[];
    float* Ast = smc;          // [128][68]
    float* Ws  = smc + 8704;   // [64][136]
    float* bs  = smc + 17408;  // [128]
    const int mt=blockIdx.x, nt=blockIdx.y, z=blockIdx.z;
    const int tid=threadIdx.x, w=tid>>5, lane=tid&31, gid=lane>>2, l4=lane&3;
    const float* W  = (z==0)?wq:((z==1)?wk:wv);
    const float* Bp = (z==0)?bq:((z==1)?bk:bv);
    float*       O  = (z==0)?pq:((z==1)?pk:pv);

    const float* Ap = g_cf + mt*128*64;
    #pragma unroll
    for (int i=0;i<8;i++){
        int idx=i*256+tid, row=idx>>4, c4=(idx&15)*4;
        *(float4*)(Ast + row*68 + c4) = *(const float4*)(Ap + row*64 + c4);
    }
    #pragma unroll
    for (int i=0;i<8;i++){
        int idx=i*256+tid, row=idx>>5, c4=(idx&31)*4;
        *(float4*)(Ws + row*136 + c4) = *(const float4*)(W + row*256 + nt*128 + c4);
    }
    if (tid<128) bs[tid] = Bp[nt*128+tid];
    __syncthreads();

    unsigned af[8][4];
    const int r0 = w*16;
    #pragma unroll
    for (int kk=0;kk<8;kk++){
        af[kk][0]=__float_as_uint(Ast[(r0+gid  )*68 + kk*8   + l4]);
        af[kk][1]=__float_as_uint(Ast[(r0+gid+8)*68 + kk*8   + l4]);
        af[kk][2]=__float_as_uint(Ast[(r0+gid  )*68 + kk*8+4 + l4]);
        af[kk][3]=__float_as_uint(Ast[(r0+gid+8)*68 + kk*8+4 + l4]);
    }
    float c[16][4];
    #pragma unroll
    for (int j=0;j<16;j++){ c[j][0]=c[j][1]=c[j][2]=c[j][3]=0.f; }
    #pragma unroll
    for (int j=0;j<16;j++){
        #pragma unroll
        for (int kk=0;kk<8;kk++){
            unsigned b0=__float_as_uint(Ws[(kk*8+l4  )*136 + j*8+gid]);
            unsigned b1=__float_as_uint(Ws[(kk*8+l4+4)*136 + j*8+gid]);
            MMA_TF32(c[j][0],c[j][1],c[j][2],c[j][3],
                     af[kk][0],af[kk][1],af[kk][2],af[kk][3],b0,b1);
        }
    }
    const int row_lo = mt*128 + r0 + gid;
    const int bidx = row_lo>>10, s_lo = row_lo&1023;
    #pragma unroll
    for (int j=0;j<16;j++){
        int cl = j*8 + 2*l4;
        int col0 = nt*128 + cl;           // even -> col0,col0+1 same head
        int h = col0>>6, d0 = col0&63, d1 = d0+1;
        float* op = O + (((bidx<<2)+h)<<16);
        float v00 = tf32r(c[j][0]+bs[cl]);
        float v01 = tf32r(c[j][1]+bs[cl+1]);
        float v10 = tf32r(c[j][2]+bs[cl]);
        float v11 = tf32r(c[j][3]+bs[cl+1]);
        if (z < 2){
            int dp0 = (d0&56)|((d0&3)<<1)|((d0&4)>>2);
            int dp1 = (d1&56)|((d1&3)<<1)|((d1&4)>>2);
            op[ s_lo   *64 + dp0] = v00;
            op[ s_lo   *64 + dp1] = v01;
            op[(s_lo+8)*64 + dp0] = v10;
            op[(s_lo+8)*64 + dp1] = v11;
        } else {
            op[d0*1024 + s_lo  ] = v00;
            op[d1*1024 + s_lo  ] = v01;
            op[d0*1024 + s_lo+8] = v10;
            op[d1*1024 + s_lo+8] = v11;
        }
    }
}

// ========== Kernel D: tf32 mma flash attention (2 CTAs/SM) ================
// K/V tiles 64 rows, pad 72, double-buffered depth-2 cp.async.
// Q/K d-interleaved -> paired LDS.64 fragments; V transposed -> P feeds PV
// directly from S accum regs (no shuffles). smem = 73,728 B.
__global__ __launch_bounds__(256, 2) void kD()
{
    extern __shared__ float sm[];
    float* KS0 = sm;             // [64][72]
    float* VS0 = sm + 4608;      // [64][72]  (V^T tile: [d][s])
    float* KS1 = sm + 9216;      // [64][72]
    float* VS1 = sm + 13824;     // [64][72]
    float* Qst = sm;             // alias [128][72] (used before K/V loads)

    const int qt=blockIdx.x, h=blockIdx.y, b=blockIdx.z;
    const int tid=threadIdx.x, w=tid>>5, lane=tid&31;
    const int gid=lane>>2, l4=lane&3;
    const int base=((b*4+h)<<16);

    const float* Kg = g_k + base;
    const float* Vg = g_v + base;          // [64 d][1024 s]
    const float* Qg = g_q + base + qt*8192;

    // stage Q (scaled by 1/sqrt(64)); g_q already tf32-rounded + d-interleaved
    #pragma unroll
    for (int i=0;i<8;i++){
        int idx=i*256+tid, row=idx>>4, c4=(idx&15)*4;
        float4 v = *(const float4*)(Qg + row*64 + c4);
        Qst[row*72+c4+0]=v.x*0.125f; Qst[row*72+c4+1]=v.y*0.125f;
        Qst[row*72+c4+2]=v.z*0.125f; Qst[row*72+c4+3]=v.w*0.125f;
    }
    __syncthreads();
    unsigned qf[8][4];
    const int r0 = w*16;
    #pragma unroll
    for (int kk=0;kk<8;kk++){
        float2 lo = *(const float2*)(Qst + (r0+gid  )*72 + kk*8 + 2*l4);
        float2 hi = *(const float2*)(Qst + (r0+gid+8)*72 + kk*8 + 2*l4);
        qf[kk][0]=__float_as_uint(lo.x); qf[kk][1]=__float_as_uint(hi.x);
        qf[kk][2]=__float_as_uint(lo.y); qf[kk][3]=__float_as_uint(hi.y);
    }
    __syncthreads();   // done reading Qst before K/V overwrite

    // prefetch tiles 0 and 1 (1024 cp16 per K tile, 1024 per V tile)
    #pragma unroll
    for (int i=0;i<4;i++){
        int idx=i*256+tid, row=idx>>4, c4=(idx&15)*4;
        cp16(KS0 + row*72 + c4, Kg + row*64 + c4);
        cp16(VS0 + row*72 + c4, Vg + row*1024 + c4);
    }
    CP_COMMIT;
    #pragma unroll
    for (int i=0;i<4;i++){
        int idx=i*256+tid, row=idx>>4, c4=(idx&15)*4;
        cp16(KS1 + row*72 + c4, Kg + 4096 + row*64 + c4);
        cp16(VS1 + row*72 + c4, Vg + 64 + row*1024 + c4);
    }
    CP_COMMIT;

    float o[8][4];
    #pragma unroll
    for (int n=0;n<8;n++){ o[n][0]=o[n][1]=o[n][2]=o[n][3]=0.f; }
    float m_lo=-1e30f, m_hi=-1e30f, l_lo=0.f, l_hi=0.f;

    for (int kt=0; kt<16; kt++){
        CP_WAIT1;
        __syncthreads();
        const float* Ks_ = (kt&1) ? KS1 : KS0;
        const float* Vs_ = (kt&1) ? VS1 : VS0;

        // ---- S = Q K^T  (16x64 per warp), paired LDS.64 B-frags ----
        float c[8][4];
        #pragma unroll
        for (int j=0;j<8;j++){ c[j][0]=c[j][1]=c[j][2]=c[j][3]=0.f; }
        #pragma unroll
        for (int j=0;j<8;j++){
            #pragma unroll
            for (int kk=0;kk<8;kk++){
                float2 bb = *(const float2*)(Ks_ + (j*8+gid)*72 + kk*8 + 2*l4);
                MMA_TF32(c[j][0],c[j][1],c[j][2],c[j][3],
                         qf[kk][0],qf[kk][1],qf[kk][2],qf[kk][3],
                         __float_as_uint(bb.x),__float_as_uint(bb.y));
            }
        }

        // ---- online softmax ----
        float mx_lo=-1e30f, mx_hi=-1e30f;
        #pragma unroll
        for (int j=0;j<8;j++){
            mx_lo = fmaxf(mx_lo, fmaxf(c[j][0], c[j][1]));
            mx_hi = fmaxf(mx_hi, fmaxf(c[j][2], c[j][3]));
        }
        mx_lo = fmaxf(mx_lo, __shfl_xor_sync(0xffffffffu, mx_lo, 1));
        mx_lo = fmaxf(mx_lo, __shfl_xor_sync(0xffffffffu, mx_lo, 2));
        mx_hi = fmaxf(mx_hi, __shfl_xor_sync(0xffffffffu, mx_hi, 1));
        mx_hi = fmaxf(mx_hi, __shfl_xor_sync(0xffffffffu, mx_hi, 2));
        float mn_lo = fmaxf(m_lo, mx_lo), mn_hi = fmaxf(m_hi, mx_hi);
        float al = __expf(m_lo - mn_lo), ah = __expf(m_hi - mn_hi);
        float s_lo=0.f, s_hi=0.f;
        #pragma unroll
        for (int j=0;j<8;j++){
            c[j][0]=__expf(c[j][0]-mn_lo); s_lo+=c[j][0];
            c[j][1]=__expf(c[j][1]-mn_lo); s_lo+=c[j][1];
            c[j][2]=__expf(c[j][2]-mn_hi); s_hi+=c[j][2];
            c[j][3]=__expf(c[j][3]-mn_hi); s_hi+=c[j][3];
        }
        s_lo += __shfl_xor_sync(0xffffffffu, s_lo, 1);
        s_lo += __shfl_xor_sync(0xffffffffu, s_lo, 2);
        s_hi += __shfl_xor_sync(0xffffffffu, s_hi, 1);
        s_hi += __shfl_xor_sync(0xffffffffu, s_hi, 2);
        l_lo = l_lo*al + s_lo;  l_hi = l_hi*ah + s_hi;
        m_lo = mn_lo;           m_hi = mn_hi;
        #pragma unroll
        for (int n=0;n<8;n++){
            o[n][0]*=al; o[n][1]*=al; o[n][2]*=ah; o[n][3]*=ah;
        }

        // ---- O += P V : P A-frags are (c0,c2,c1,c3) directly (no shuffles),
        //      V^T in smem gives paired LDS.64 B-frags ----
        #pragma unroll
        for (int t=0;t<8;t++){
            unsigned a0 = tf32u(c[t][0]);
            unsigned a1 = tf32u(c[t][2]);
            unsigned a2 = tf32u(c[t][1]);
            unsigned a3 = tf32u(c[t][3]);
            #pragma unroll
            for (int n=0;n<8;n++){
                float2 bb = *(const float2*)(Vs_ + (n*8+gid)*72 + t*8 + 2*l4);
                MMA_TF32(o[n][0],o[n][1],o[n][2],o[n][3],a0,a1,a2,a3,
                         __float_as_uint(bb.x),__float_as_uint(bb.y));
            }
        }

        __syncthreads();   // all warps done with buf[kt&1]
        if (kt < 14){
            const float* Kp = Kg + (kt+2)*4096;
            const float* Vp = Vg + (kt+2)*64;
            float* kd = (kt&1) ? KS1 : KS0;
            float* vd = (kt&1) ? VS1 : VS0;
            #pragma unroll
            for (int i=0;i<4;i++){
                int idx=i*256+tid, row=idx>>4, c4=(idx&15)*4;
                cp16(kd + row*72 + c4, Kp + row*64 + c4);
                cp16(vd + row*72 + c4, Vp + row*1024 + c4);
            }
        }
        CP_COMMIT;   // empty group when kt>=14 keeps group accounting uniform
    }

    float il = 1.f/l_lo, ih = 1.f/l_hi;
    float* Op = g_o + base + qt*8192;
    const int r_lo = r0 + gid, r_hi = r_lo + 8;
    #pragma unroll
    for (int n=0;n<8;n++){
        int col = n*8 + 2*l4;
        *(float2*)(Op + r_lo*64 + col) = make_float2(o[n][0]*il, o[n][1]*il);
        *(float2*)(Op + r_hi*64 + col) = make_float2(o[n][2]*ih, o[n][3]*ih);
    }
}

// ==== Kernel E: out-proj GEMM [*,256]@[256,64] + residual + LN + transpose =
__global__ __launch_bounds__(256) void kE(const float* __restrict__ fc,
                                          const float* __restrict__ fcb,
                                          const float* __restrict__ lng,
                                          const float* __restrict__ lnb,
                                          float* __restrict__ out)
{
    __shared__ __align__(16) float As[64*68];
    __shared__ __align__(16) float Bs[64*68];
    float* Cs = Bs;
    const int stile = blockIdx.x, b = blockIdx.y, tid = threadIdx.x;
    const int tx = tid&15, ty = tid>>4;
    const int s0 = stile*64;

    float accv[4][4] = {};
    for (int h=0; h<4; h++){
        __syncthreads();
        const float* Ap = g_o + ((b*4+h)<<16) + s0*64;
        #pragma unroll
        for (int i=0;i<4;i++){
            int idx=i*256+tid, row=idx>>4, c4=(idx&15)*4;
            *(float4*)(As + row*68 + c4) = *(const float4*)(Ap + row*64 + c4);
            *(float4*)(Bs + row*68 + c4) = *(const float4*)(fc + (h*64+row)*64 + c4);
        }
        __syncthreads();
        #pragma unroll 8
        for (int k=0;k<64;k++){
            float a[4];
            #pragma unroll
            for (int i=0;i<4;i++) a[i] = As[(4*ty+i)*68 + k];
            float4 bb = *(const float4*)(Bs + k*68 + 4*tx);
            #pragma unroll
            for (int i=0;i<4;i++){
                accv[i][0] = fmaf(a[i], bb.x, accv[i][0]);
                accv[i][1] = fmaf(a[i], bb.y, accv[i][1]);
                accv[i][2] = fmaf(a[i], bb.z, accv[i][2]);
                accv[i][3] = fmaf(a[i], bb.w, accv[i][3]);
            }
        }
    }
    __syncthreads();
    #pragma unroll
    for (int i=0;i<4;i++){
        int r = 4*ty + i;
        #pragma unroll
        for (int j=0;j<4;j++){
            int c = 4*tx + j;
            Cs[r*68+c] = accv[i][j] + fcb[c] + g_cf[b*65536 + (s0+r)*64 + c];
        }
    }
    __syncthreads();
    {
        const int wid = tid>>5, lane = tid&31;
        for (int rr=0; rr<8; rr++){
            int r = wid*8 + rr;
            float v0 = Cs[r*68+lane], v1 = Cs[r*68+lane+32];
            float sm = v0+v1, sq = v0*v0 + v1*v1;
            #pragma unroll
            for (int off=16; off; off>>=1){
                sm += __shfl_xor_sync(0xffffffffu, sm, off);
                sq += __shfl_xor_sync(0xffffffffu, sq, off);
            }
            float mu = sm*(1.f/64.f);
            float var = sq*(1.f/64.f) - mu*mu;
            float rstd = rsqrtf(var + 1e-6f);
            Cs[r*68+lane]    = (v0-mu)*rstd*lng[lane]    + lnb[lane];
            Cs[r*68+lane+32] = (v1-mu)*rstd*lng[lane+32] + lnb[lane+32];
        }
    }
    __syncthreads();
    #pragma unroll
    for (int i=0;i<16;i++){
        int idx = i*256 + tid;
        int c = idx>>6, sl = idx&63;
        out[(((b<<6)+c)<<10) + s0 + sl] = Cs[sl*68+c];
    }
}

// ============================== launcher ===================================
extern "C" void kernel_launch(void* const* d_in, const int* in_sizes, int n_in,
                              void* d_out, int out_size)
{
    const float* x      = (const float*)d_in[0];
    const float* memory = (const float*)d_in[1];
    const float* wb_w   = (const float*)d_in[2];
    const float* wb_b   = (const float*)d_in[3];
    const float* a1_wq  = (const float*)d_in[4];
    const float* a1_bq  = (const float*)d_in[5];
    const float* a1_wk  = (const float*)d_in[6];
    const float* a1_bk  = (const float*)d_in[7];
    const float* a1_wv  = (const float*)d_in[8];
    const float* a1_bv  = (const float*)d_in[9];
    const float* a1_fc  = (const float*)d_in[10];
    const float* a1_fcb = (const float*)d_in[11];
    const float* a1_lng = (const float*)d_in[12];
    const float* a1_lnb = (const float*)d_in[13];
    const float* a2_wq  = (const float*)d_in[14];
    const float* a2_bq  = (const float*)d_in[15];
    const float* a2_wk  = (const float*)d_in[16];
    const float* a2_bk  = (const float*)d_in[17];
    const float* a2_wv  = (const float*)d_in[18];
    const float* a2_bv  = (const float*)d_in[19];
    const float* a2_fc  = (const float*)d_in[20];
    const float* a2_fcb = (const float*)d_in[21];
    const float* a2_lng = (const float*)d_in[22];
    const float* a2_lnb = (const float*)d_in[23];
    float* out = (float*)d_out;

    float *pq=0, *pk=0, *pv=0;
    cudaGetSymbolAddress((void**)&pq, g_q);
    cudaGetSymbolAddress((void**)&pk, g_k);
    cudaGetSymbolAddress((void**)&pv, g_v);

    const int kcm_smem = 17536*4;    // 70144 B
    const int kd_smem  = 18432*4;    // 73728 B -> 2 CTAs/SM
    cudaFuncSetAttribute(kCm, cudaFuncAttributeMaxDynamicSharedMemorySize, kcm_smem);
    cudaFuncSetAttribute(kD,  cudaFuncAttributeMaxDynamicSharedMemorySize, kd_smem);

    kA<<<NB, 1024>>>(x, wb_w, wb_b);
    kB<<<NB, 512>>>(x, memory, a1_wq, a1_bq, a1_wk, a1_bk, a1_wv, a1_bv,
                    a1_fc, a1_fcb, a1_lng, a1_lnb);
    dim3 gC(128, 2, 3);
    kCm<<<gC, 256, kcm_smem>>>(a2_wq, a2_wk, a2_wv, a2_bq, a2_bk, a2_bv, pq, pk, pv);
    dim3 gD(8, 4, NB);
    kD<<<gD, 256, kd_smem>>>();
    dim3 gE(16, NB);
    kE<<<gE, 256>>>(a2_fc, a2_fcb, a2_lng, a2_lnb, out);
}